// round 7
// baseline (speedup 1.0000x reference)
#include <cuda_runtime.h>
#include <cuda_fp16.h>
#include <cstdint>

// Problem constants
#define Bn  8
#define Cc  512
#define Ln  4096
#define Hh  8
#define Dh  64
#define NSPLIT 4

// ---------------------------------------------------------------------------
// Scratch
// ---------------------------------------------------------------------------
__device__ float g_scratch[135266304];
__device__ __half g_hf[102760448];

// half-element offsets into g_hf
#define OFF_Z1C  0ull
#define OFF_Z2C  16777216ull
#define OFF_ATTC 33554432ull
#define OFF_ZC   50331648ull
#define OFF_HC   67108864ull
#define OFF_WQ   100663296ull
#define OFF_WK   100925440ull
#define OFF_WV   101187584ull
#define OFF_WR   101449728ull
#define OFF_W1   101711872ull
#define OFF_W2   102236160ull

// ---------------------------------------------------------------------------
// Helpers
// ---------------------------------------------------------------------------
__device__ __forceinline__ uint32_t smem_u32(const void* p) {
    uint32_t a;
    asm("{ .reg .u64 t; cvta.to.shared.u64 t, %1; cvt.u32.u64 %0, t; }"
        : "=r"(a) : "l"(p));
    return a;
}
__device__ __host__ __forceinline__ uint32_t swz128(uint32_t off) {
    return off ^ ((off >> 3) & 0x70);
}
__device__ __forceinline__ void cpasync16(uint32_t d, const void* s) {
    asm volatile("cp.async.cg.shared.global [%0], [%1], 16;" :: "r"(d), "l"(s));
}
#define CP_COMMIT() asm volatile("cp.async.commit_group;" ::: "memory")
#define CP_WAIT(N)  asm volatile("cp.async.wait_group " #N ";" ::: "memory")

#define LDSM4(R, ADDR) \
    asm volatile("ldmatrix.sync.aligned.m8n8.x4.shared.b16 {%0,%1,%2,%3}, [%4];" \
        : "=r"((R)[0]), "=r"((R)[1]), "=r"((R)[2]), "=r"((R)[3]) : "r"(ADDR))

#define MMA16816(C, A, Bv) \
    asm volatile("mma.sync.aligned.m16n8k16.row.col.f32.f16.f16.f32 " \
        "{%0,%1,%2,%3}, {%4,%5,%6,%7}, {%8,%9}, {%0,%1,%2,%3};" \
        : "+f"((C)[0]), "+f"((C)[1]), "+f"((C)[2]), "+f"((C)[3]) \
        : "r"((A)[0]), "r"((A)[1]), "r"((A)[2]), "r"((A)[3]), \
          "r"((Bv)[0]), "r"((Bv)[1]))

__device__ __forceinline__ uint32_t pack2h(float a, float b) {
    __half2 h = __floats2half2_rn(a, b);
    return *(uint32_t*)&h;
}

// ---------------------------------------------------------------------------
// Convert ALL weights in one launch.
// grid (16, 8, 6): widx = blockIdx.z selects weight; out-of-range blocks exit.
// Per-block work identical to old conv_w.
// ---------------------------------------------------------------------------
__global__ __launch_bounds__(256) void conv_w_all(
    const float* __restrict__ Wq, const float* __restrict__ Wk,
    const float* __restrict__ Wv, const float* __restrict__ Wr,
    const float* __restrict__ W1, const float* __restrict__ W2,
    __half* __restrict__ hf)
{
    int widx = blockIdx.z;
    const float* src;
    __half* dstb;
    int K, MT;   // K dim, tiles in M
    switch (widx) {
        case 0: src = Wq; dstb = hf + OFF_WQ; K = 512;  MT = 4; break;
        case 1: src = Wk; dstb = hf + OFF_WK; K = 512;  MT = 4; break;
        case 2: src = Wv; dstb = hf + OFF_WV; K = 512;  MT = 4; break;
        case 3: src = Wr; dstb = hf + OFF_WR; K = 512;  MT = 4; break;
        case 4: src = W1; dstb = hf + OFF_W1; K = 512;  MT = 8; break;
        default: src = W2; dstb = hf + OFF_W2; K = 1024; MT = 4; break;
    }
    int NC = K >> 6;
    int kc = blockIdx.x, mt = blockIdx.y;
    if (kc >= NC || mt >= MT) return;
    char* db = (char*)(dstb + ((size_t)(mt * NC + kc)) * 8192);
    const float* sb = src + ((size_t)mt * 128) * K + kc * 64;
    for (int it = 0; it < 4; it++) {
        int u = threadIdx.x + 256 * it;
        int r = u >> 3, g = u & 7;
        float x0[8];
        #pragma unroll
        for (int q = 0; q < 2; q++) {
            float4 v = *(const float4*)(sb + (size_t)r * K + g * 8 + q * 4);
            x0[q*4+0]=v.x; x0[q*4+1]=v.y; x0[q*4+2]=v.z; x0[q*4+3]=v.w;
        }
        uint4 w;
        w.x = pack2h(x0[0], x0[1]);
        w.y = pack2h(x0[2], x0[3]);
        w.z = pack2h(x0[4], x0[5]);
        w.w = pack2h(x0[6], x0[7]);
        uint32_t sw = swz128((uint32_t)r * 128 + g * 16);
        *(uint4*)(db + sw) = w;
    }
}

// ---------------------------------------------------------------------------
// Convert+transpose both z1 and z2 in one launch: grid (8, 16, 16);
// blockIdx.z < 8 -> z1 -> dst1, else z2 -> dst2.
// ---------------------------------------------------------------------------
__global__ __launch_bounds__(256) void conv_x2(
    const float* __restrict__ src1, const float* __restrict__ src2,
    __half* __restrict__ dst1, __half* __restrict__ dst2)
{
    const int K = 512;
    int kc = blockIdx.x, lt = blockIdx.y;
    int b = blockIdx.z & 7;
    const float* src = (blockIdx.z < 8) ? src1 : src2;
    __half* dstb = (blockIdx.z < 8) ? dst1 : dst2;
    int NC = K >> 6;
    __shared__ float sm[32][264];
    const float* sb = src + ((size_t)b * K + kc * 64) * Ln + (size_t)lt * 256;
    char* db = (char*)(dstb + (((size_t)b * 16 + lt) * NC + kc) * 16384);
    int t = threadIdx.x;
    for (int p = 0; p < 2; p++) {
        __syncthreads();
        #pragma unroll
        for (int i = 0; i < 8; i++) {
            int u = t + 256 * i;
            int kr = u >> 6;
            int lc = u & 63;
            float4 v = *(const float4*)(sb + ((size_t)(p * 32 + kr)) * Ln + lc * 4);
            sm[kr][lc*4+0]=v.x; sm[kr][lc*4+1]=v.y; sm[kr][lc*4+2]=v.z; sm[kr][lc*4+3]=v.w;
        }
        __syncthreads();
        #pragma unroll
        for (int g = 0; g < 4; g++) {
            float x0[8];
            #pragma unroll
            for (int j = 0; j < 8; j++) x0[j] = sm[g*8+j][t];
            uint4 w;
            w.x = pack2h(x0[0], x0[1]);
            w.y = pack2h(x0[2], x0[3]);
            w.z = pack2h(x0[4], x0[5]);
            w.w = pack2h(x0[6], x0[7]);
            uint32_t sw = swz128((uint32_t)t * 128 + (p * 32 + g * 8) * 2);
            *(uint4*)(db + sw) = w;
        }
    }
}

// ---------------------------------------------------------------------------
// Warp-MMA fp16 GEMM: 128 threads, 4 warps of 64x64, CTA tile 128(m)x128(l).
// outmode 0: fp32 Out (+Res)(+ELU). outmode 1: fp16 tiled Outh (+ELU).
// ---------------------------------------------------------------------------
__global__ __launch_bounds__(128, 2) void gemm_wm(
    const __half* __restrict__ Wc, const float* __restrict__ bias,
    const __half* __restrict__ Xc, float* __restrict__ Out,
    __half* __restrict__ Outh,
    const float* __restrict__ Res, int M, int K, int act, int outmode)
{
    extern __shared__ __align__(1024) char smem[];
    const int NC = K >> 6;
    int tid = threadIdx.x, wid = tid >> 5, lane = tid & 31;
    int mt = blockIdx.x, lt = blockIdx.y, b = blockIdx.z;
    int wm = wid >> 1, wn = wid & 1;          // 2x2 warp grid, 64x64 each
    int sub = lane >> 3, r = lane & 7;

    const char* Abase = (const char*)Wc + ((size_t)mt * NC) * 16384;
    int lt256 = lt >> 1, half = lt & 1;
    const char* Bbase = (const char*)Xc + (((size_t)b * 16 + lt256) * NC) * 32768
                        + (size_t)half * 16384;

    uint32_t sbase = smem_u32(smem);

    // A: 4 x4-tiles covering 64 m rows x 16 k
    uint32_t aRow[4], aMask[4];
    int kaddA = (sub >> 1) * 16;
    #pragma unroll
    for (int i = 0; i < 4; i++) {
        uint32_t row = wm * 64 + i * 16 + (sub & 1) * 8 + r;
        aRow[i] = row * 128;
        aMask[i] = (aRow[i] >> 3) & 0x70;
    }
    // B: 4 x4-tiles covering 64 l rows x 16 k
    uint32_t bRow[4], bMask[4];
    int kaddB = (sub & 1) * 16;
    #pragma unroll
    for (int j = 0; j < 4; j++) {
        uint32_t row = wn * 64 + j * 16 + (sub >> 1) * 8 + r;
        bRow[j] = row * 128;
        bMask[j] = (bRow[j] >> 3) & 0x70;
    }

    float acc[4][8][4];
    #pragma unroll
    for (int i = 0; i < 4; i++)
        #pragma unroll
        for (int j = 0; j < 8; j++)
            #pragma unroll
            for (int q = 0; q < 4; q++) acc[i][j][q] = 0.f;

    // Stage: [A 16K][B 16K] = 32KB; 128 threads load 256B each
    auto load_stage = [&](int kc, int s) {
        uint32_t S = sbase + (uint32_t)s * 32768;
        const char* ah = Abase + (size_t)kc * 16384;
        const char* bh = Bbase + (size_t)kc * 32768;
        #pragma unroll
        for (int q = 0; q < 8; q++) {
            uint32_t off = (uint32_t)tid * 128 + q * 16;
            cpasync16(S + off,         ah + off);
            cpasync16(S + 16384 + off, bh + off);
        }
    };

    load_stage(0, 0);
    CP_COMMIT();

    for (int c = 0; c < NC; c++) {
        if (c + 1 < NC) {
            load_stage(c + 1, (c + 1) & 1);
            CP_COMMIT();
            CP_WAIT(1);
        } else {
            CP_WAIT(0);
        }
        __syncthreads();

        uint32_t S = sbase + (uint32_t)(c & 1) * 32768;
        #pragma unroll
        for (int kk = 0; kk < 4; kk++) {
            int kb = kk * 32;
            uint32_t aa[16], bb[16];
            #pragma unroll
            for (int i = 0; i < 4; i++)
                LDSM4(&aa[i * 4], S + aRow[i] + (uint32_t)((kaddA + kb) ^ aMask[i]));
            #pragma unroll
            for (int j = 0; j < 4; j++)
                LDSM4(&bb[j * 4], S + 16384 + bRow[j] + (uint32_t)((kaddB + kb) ^ bMask[j]));
            #pragma unroll
            for (int mi = 0; mi < 4; mi++)
                #pragma unroll
                for (int nj = 0; nj < 8; nj++)
                    MMA16816(acc[mi][nj], &aa[mi * 4], &bb[nj * 2]);
        }
        __syncthreads();
    }

    int g = lane >> 2, tg = lane & 3;

    if (outmode == 0) {
        #pragma unroll
        for (int mi = 0; mi < 4; mi++) {
            #pragma unroll
            for (int h2 = 0; h2 < 2; h2++) {
                int m = mt * 128 + wm * 64 + mi * 16 + h2 * 8 + g;
                float bi = bias[m];
                size_t rowoff = ((size_t)b * M + m) * Ln + (size_t)lt * 128 + wn * 64;
                #pragma unroll
                for (int nj = 0; nj < 8; nj++) {
                    int col = nj * 8 + 2 * tg;
                    float v0 = acc[mi][nj][h2 * 2 + 0] + bi;
                    float v1 = acc[mi][nj][h2 * 2 + 1] + bi;
                    if (Res) {
                        float2 r2 = *(const float2*)(Res + rowoff + col);
                        v0 += r2.x; v1 += r2.y;
                    }
                    if (act) {
                        v0 = v0 > 0.f ? v0 : expm1f(v0);
                        v1 = v1 > 0.f ? v1 : expm1f(v1);
                    }
                    *(float2*)(Out + rowoff + col) = make_float2(v0, v1);
                }
            }
        }
    } else {
        // Stage fp16 tile transposed: rows l (0..127), pitch 136 halves
        __half* smh = (__half*)smem;
        #pragma unroll
        for (int mi = 0; mi < 4; mi++) {
            #pragma unroll
            for (int h2 = 0; h2 < 2; h2++) {
                int ml = wm * 64 + mi * 16 + h2 * 8 + g;
                float bi = bias[mt * 128 + ml];
                #pragma unroll
                for (int nj = 0; nj < 8; nj++) {
                    int ll = wn * 64 + nj * 8 + 2 * tg;
                    float v0 = acc[mi][nj][h2 * 2 + 0] + bi;
                    float v1 = acc[mi][nj][h2 * 2 + 1] + bi;
                    if (act) {
                        v0 = v0 > 0.f ? v0 : expm1f(v0);
                        v1 = v1 > 0.f ? v1 : expm1f(v1);
                    }
                    smh[(uint32_t)ll * 136 + ml]       = __float2half(v0);
                    smh[(uint32_t)(ll + 1) * 136 + ml] = __float2half(v1);
                }
            }
        }
        __syncthreads();
        int rowbase = (lt & 1) * 128;
        int NCo = M >> 6;
        #pragma unroll
        for (int kc = 0; kc < 2; kc++) {
            char* db = (char*)(Outh + (((size_t)b * 16 + lt256) * NCo + (mt * 2 + kc)) * 16384);
            #pragma unroll
            for (int it = 0; it < 8; it++) {
                int u = tid + 128 * it;          // 0..1023
                int row = u >> 3, j = u & 7;
                uint4 w = *(uint4*)&smh[(uint32_t)row * 136 + kc * 64 + j * 8];
                *(uint4*)(db + swz128((uint32_t)(rowbase + row) * 128 + j * 16)) = w;
            }
        }
    }
}

// ---------------------------------------------------------------------------
// Softmax over length (contiguous Ln rows)
// ---------------------------------------------------------------------------
__global__ __launch_bounds__(256) void softmax_len(float* __restrict__ data)
{
    __shared__ float red[256];
    float* p = data + (size_t)blockIdx.x * Ln;
    int t = threadIdx.x;
    float v[16];
    float m = -1e30f;
    #pragma unroll
    for (int i = 0; i < 16; i++) { v[i] = p[t + 256 * i]; m = fmaxf(m, v[i]); }
    red[t] = m; __syncthreads();
    for (int off = 128; off > 0; off >>= 1) {
        if (t < off) red[t] = fmaxf(red[t], red[t + off]);
        __syncthreads();
    }
    m = red[0];
    __syncthreads();
    float s = 0.f;
    #pragma unroll
    for (int i = 0; i < 16; i++) { v[i] = __expf(v[i] - m); s += v[i]; }
    red[t] = s; __syncthreads();
    for (int off = 128; off > 0; off >>= 1) {
        if (t < off) red[t] += red[t + off];
        __syncthreads();
    }
    float inv = 1.f / red[0];
    #pragma unroll
    for (int i = 0; i < 16; i++) p[t + 256 * i] = v[i] * inv;
}

// ---------------------------------------------------------------------------
// ctx partials
// ---------------------------------------------------------------------------
__global__ __launch_bounds__(256) void ctx_kernel(
    const float* __restrict__ kk, const float* __restrict__ vv,
    float* __restrict__ ctxp)
{
    int bh = blockIdx.x;
    int sp = blockIdx.y;
    const float* kb = kk + (size_t)bh * Dh * Ln;
    const float* vb = vv + (size_t)bh * Dh * Ln;

    __shared__ float ks[64][33];
    __shared__ float vs[64][33];

    int tid = threadIdx.x;
    int lt = tid & 31, dr = tid >> 5;
    int tx = tid & 15, ty = tid >> 4;

    float acc[4][4];
    #pragma unroll
    for (int i = 0; i < 4; i++)
        #pragma unroll
        for (int j = 0; j < 4; j++) acc[i][j] = 0.f;

    int lbeg = sp * (Ln / NSPLIT);
    int lend = lbeg + (Ln / NSPLIT);
    for (int l0 = lbeg; l0 < lend; l0 += 32) {
        __syncthreads();
        #pragma unroll
        for (int r = 0; r < 8; r++) {
            int dk = dr + 8 * r;
            ks[dk][lt] = kb[(size_t)dk * Ln + l0 + lt];
            vs[dk][lt] = vb[(size_t)dk * Ln + l0 + lt];
        }
        __syncthreads();
        #pragma unroll
        for (int l2 = 0; l2 < 32; l2++) {
            float av[4], bw[4];
            #pragma unroll
            for (int i = 0; i < 4; i++) av[i] = ks[ty * 4 + i][l2];
            #pragma unroll
            for (int j = 0; j < 4; j++) bw[j] = vs[tx * 4 + j][l2];
            #pragma unroll
            for (int i = 0; i < 4; i++)
                #pragma unroll
                for (int j = 0; j < 4; j++)
                    acc[i][j] += av[i] * bw[j];
        }
    }
    #pragma unroll
    for (int i = 0; i < 4; i++)
        #pragma unroll
        for (int j = 0; j < 4; j++) {
            int dk = ty * 4 + i, dv = tx * 4 + j;
            ctxp[(((size_t)sp * 64 + bh) * 64 + dk) * 64 + dv] = acc[i][j];
        }
}

// ---------------------------------------------------------------------------
// att fused: head-softmax(q) inline + ctx^T apply + fp16 tiled output
// ---------------------------------------------------------------------------
__global__ __launch_bounds__(256) void att_fused(
    const float* __restrict__ ctxp, const float* __restrict__ q,
    __half* __restrict__ attc)
{
    int bh = blockIdx.y;
    int b = bh >> 3, h = bh & 7;
    __shared__ float cs[64][64];
    int tid = threadIdx.x;

    float4* cs4 = (float4*)cs;
    #pragma unroll
    for (int r = 0; r < 4; r++) {
        int idx = tid + 256 * r;
        float4 sum = make_float4(0.f, 0.f, 0.f, 0.f);
        #pragma unroll
        for (int s = 0; s < NSPLIT; s++) {
            const float4* p = (const float4*)(ctxp + ((size_t)s * 64 + bh) * 4096);
            float4 t = p[idx];
            sum.x += t.x; sum.y += t.y; sum.z += t.z; sum.w += t.w;
        }
        cs4[idx] = sum;
    }
    __syncthreads();

    int l = blockIdx.x * 256 + tid;
    const float* qb = q + (size_t)bh * Dh * Ln + l;

    float qv[64];
    float mx = -1e30f;
    #pragma unroll
    for (int d = 0; d < 64; d++) { qv[d] = qb[(size_t)d * Ln]; mx = fmaxf(mx, qv[d]); }
    float s = 0.f;
    #pragma unroll
    for (int d = 0; d < 64; d++) { qv[d] = __expf(qv[d] - mx); s += qv[d]; }
    float inv = 1.f / s;

    float acc[64];
    #pragma unroll
    for (int d = 0; d < 64; d++) acc[d] = 0.f;

    #pragma unroll 4
    for (int dk = 0; dk < 64; dk++) {
        float qq = qv[dk] * inv;
        #pragma unroll
        for (int j = 0; j < 16; j++) {
            float4 c4 = *(const float4*)&cs[dk][j * 4];
            acc[4 * j + 0] += c4.x * qq;
            acc[4 * j + 1] += c4.y * qq;
            acc[4 * j + 2] += c4.z * qq;
            acc[4 * j + 3] += c4.w * qq;
        }
    }

    char* db = (char*)(attc + (((size_t)b * 16 + blockIdx.x) * 8 + h) * 16384);
    #pragma unroll
    for (int j = 0; j < 8; j++) {
        uint4 w;
        w.x = pack2h(acc[8*j+0], acc[8*j+1]);
        w.y = pack2h(acc[8*j+2], acc[8*j+3]);
        w.z = pack2h(acc[8*j+4], acc[8*j+5]);
        w.w = pack2h(acc[8*j+6], acc[8*j+7]);
        *(uint4*)(db + swz128((uint32_t)tid * 128 + j * 16)) = w;
    }
}

// ---------------------------------------------------------------------------
// Channel LayerNorm over C=512 -> fp32 out (channel-first)
// ---------------------------------------------------------------------------
__global__ __launch_bounds__(256) void ln_kernel(
    const float* __restrict__ in, float* __restrict__ out,
    const float* __restrict__ g, const float* __restrict__ be)
{
    __shared__ float ss[8][32], sq[8][32], smean[32], srstd[32];
    int blk = blockIdx.x;
    int b = blk >> 7;
    int li = threadIdx.x & 31;
    int l = ((blk & 127) << 5) + li;
    int r = threadIdx.x >> 5;
    const float* base = in + (size_t)b * Cc * Ln + l;

    float s = 0.f, s2 = 0.f;
    #pragma unroll
    for (int k2 = 0; k2 < 64; k2++) {
        int c = r * 64 + k2;
        float x = base[(size_t)c * Ln];
        s += x; s2 += x * x;
    }
    ss[r][li] = s; sq[r][li] = s2;
    __syncthreads();
    if (r == 0) {
        float ts = ss[0][li], t2 = sq[0][li];
        #pragma unroll
        for (int rr = 1; rr < 8; rr++) { ts += ss[rr][li]; t2 += sq[rr][li]; }
        float mean = ts * (1.f / 512.f);
        float var = t2 * (1.f / 512.f) - mean * mean;
        smean[li] = mean;
        srstd[li] = rsqrtf(var + 1e-5f);
    }
    __syncthreads();
    float mean = smean[li], rstd = srstd[li];
    float* ob = out + (size_t)b * Cc * Ln + l;
    #pragma unroll
    for (int k2 = 0; k2 < 64; k2++) {
        int c = r * 64 + k2;
        float x = base[(size_t)c * Ln];
        ob[(size_t)c * Ln] = (x - mean) * rstd * g[c] + be[c];
    }
}

// ---------------------------------------------------------------------------
// Channel LayerNorm -> fp16 tiled out (GEMM-input block format)
// ---------------------------------------------------------------------------
__global__ __launch_bounds__(256) void ln_h(
    const float* __restrict__ in, __half* __restrict__ outc,
    const float* __restrict__ g, const float* __restrict__ be)
{
    __shared__ float ss[8][32], sq[8][32], smean[32], srstd[32];
    int blk = blockIdx.x;
    int b = blk >> 7;
    int li = threadIdx.x & 31;
    int l = ((blk & 127) << 5) + li;
    int r = threadIdx.x >> 5;
    const float* base = in + (size_t)b * Cc * Ln + l;

    float s = 0.f, s2 = 0.f;
    float x0[64];
    #pragma unroll
    for (int k2 = 0; k2 < 64; k2++) {
        int c = r * 64 + k2;
        float x = base[(size_t)c * Ln];
        x0[k2] = x;
        s += x; s2 += x * x;
    }
    ss[r][li] = s; sq[r][li] = s2;
    __syncthreads();
    if (r == 0) {
        float ts = ss[0][li], t2 = sq[0][li];
        #pragma unroll
        for (int rr = 1; rr < 8; rr++) { ts += ss[rr][li]; t2 += sq[rr][li]; }
        float mean = ts * (1.f / 512.f);
        float var = t2 * (1.f / 512.f) - mean * mean;
        smean[li] = mean;
        srstd[li] = rsqrtf(var + 1e-5f);
    }
    __syncthreads();
    float mean = smean[li], rstd = srstd[li];

    char* db = (char*)(outc + (((size_t)b * 16 + (l >> 8)) * 8 + r) * 16384);
    uint32_t row = (uint32_t)(l & 255);
    #pragma unroll
    for (int j = 0; j < 8; j++) {
        float v[8];
        #pragma unroll
        for (int q2 = 0; q2 < 8; q2++) {
            int c = r * 64 + j * 8 + q2;
            v[q2] = (x0[j * 8 + q2] - mean) * rstd * g[c] + be[c];
        }
        uint4 w;
        w.x = pack2h(v[0], v[1]);
        w.y = pack2h(v[2], v[3]);
        w.z = pack2h(v[4], v[5]);
        w.w = pack2h(v[6], v[7]);
        *(uint4*)(db + swz128(row * 128 + j * 16)) = w;
    }
}

// ---------------------------------------------------------------------------
extern "C" void kernel_launch(void* const* d_in, const int* in_sizes, int n_in,
                              void* d_out, int out_size)
{
    const float* z1  = (const float*)d_in[0];
    const float* z2  = (const float*)d_in[1];
    const float* Wq  = (const float*)d_in[2];
    const float* bq  = (const float*)d_in[3];
    const float* Wk  = (const float*)d_in[4];
    const float* bkb = (const float*)d_in[5];
    const float* Wv  = (const float*)d_in[6];
    const float* bv  = (const float*)d_in[7];
    const float* Wr  = (const float*)d_in[8];
    const float* br  = (const float*)d_in[9];
    const float* g1  = (const float*)d_in[10];
    const float* be1 = (const float*)d_in[11];
    const float* W1  = (const float*)d_in[12];
    const float* b1  = (const float*)d_in[13];
    const float* W2  = (const float*)d_in[14];
    const float* b2  = (const float*)d_in[15];
    const float* g2  = (const float*)d_in[16];
    const float* be2 = (const float*)d_in[17];

    float* fs = nullptr;
    cudaGetSymbolAddress((void**)&fs, g_scratch);
    __half* hf = nullptr;
    cudaGetSymbolAddress((void**)&hf, g_hf);

    const size_t SZ = (size_t)Bn * Cc * Ln;   // 16777216
    float* q    = fs;
    float* k    = fs + SZ;
    float* v    = fs + 2 * SZ;
    float* z    = fs + 4 * SZ;
    float* y    = fs + 5 * SZ;
    float* ctxp = fs + 8 * SZ;

    const int GEMM_SMEM = 65536;
    cudaFuncSetAttribute(gemm_wm, cudaFuncAttributeMaxDynamicSharedMemorySize, GEMM_SMEM);

    dim3 thr(256);
    // All weight conversions in one launch
    conv_w_all<<<dim3(16, 8, 6), thr>>>(Wq, Wk, Wv, Wr, W1, W2, hf);
    // Both input conversions in one launch
    conv_x2<<<dim3(8, 16, 16), thr>>>(z1, z2, hf + OFF_Z1C, hf + OFF_Z2C);

    // Projections (warp-MMA fp16, fp32 out)
    gemm_wm<<<dim3(4, 32, 8), 128, GEMM_SMEM>>>(hf + OFF_WQ, bq,  hf + OFF_Z1C, q, nullptr, nullptr, 512, 512, 0, 0);
    gemm_wm<<<dim3(4, 32, 8), 128, GEMM_SMEM>>>(hf + OFF_WK, bkb, hf + OFF_Z2C, k, nullptr, nullptr, 512, 512, 0, 0);
    gemm_wm<<<dim3(4, 32, 8), 128, GEMM_SMEM>>>(hf + OFF_WV, bv,  hf + OFF_Z2C, v, nullptr, nullptr, 512, 512, 0, 0);

    // key softmax over length
    softmax_len<<<Bn * Cc, thr>>>(k);

    // Attention core
    ctx_kernel<<<dim3(Bn * Hh, NSPLIT), thr>>>(k, v, ctxp);
    att_fused<<<dim3(Ln / 256, Bn * Hh), thr>>>(ctxp, q, hf + OFF_ATTC);

    // Reprojection + residual (fp32 out)
    gemm_wm<<<dim3(4, 32, 8), 128, GEMM_SMEM>>>(hf + OFF_WR, br, hf + OFF_ATTC, z, nullptr, z1, 512, 512, 0, 0);

    // LN1 -> fp16 tiled
    ln_h<<<Bn * (Ln / 32), thr>>>(z, hf + OFF_ZC, g1, be1);

    // FFN1 -> fp16 tiled h (ELU fused), FFN2 -> fp32 y
    gemm_wm<<<dim3(8, 32, 8), 128, GEMM_SMEM>>>(hf + OFF_W1, b1, hf + OFF_ZC, nullptr, hf + OFF_HC, nullptr, 1024, 512, 1, 1);
    gemm_wm<<<dim3(4, 32, 8), 128, GEMM_SMEM>>>(hf + OFF_W2, b2, hf + OFF_HC, y, nullptr, nullptr, 512, 1024, 0, 0);

    // LN2 -> output
    ln_kernel<<<Bn * (Ln / 32), thr>>>(y, (float*)d_out, g2, be2);
}

// round 8
// speedup vs baseline: 1.3198x; 1.3198x over previous
#include <cuda_runtime.h>
#include <cuda_fp16.h>
#include <cstdint>

// Problem constants
#define Bn  8
#define Cc  512
#define Ln  4096
#define Hh  8
#define Dh  64
#define NSPLIT 4

// ---------------------------------------------------------------------------
// Scratch
// ---------------------------------------------------------------------------
__device__ float g_scratch[135266304];
__device__ __half g_hf[102760448];

// half-element offsets into g_hf
#define OFF_Z1C  0ull
#define OFF_Z2C  16777216ull
#define OFF_ATTC 33554432ull
#define OFF_ZC   50331648ull
#define OFF_HC   67108864ull
#define OFF_WQ   100663296ull
#define OFF_WK   100925440ull
#define OFF_WV   101187584ull
#define OFF_WR   101449728ull
#define OFF_W1   101711872ull
#define OFF_W2   102236160ull

// ---------------------------------------------------------------------------
// Helpers
// ---------------------------------------------------------------------------
__device__ __forceinline__ uint32_t smem_u32(const void* p) {
    uint32_t a;
    asm("{ .reg .u64 t; cvta.to.shared.u64 t, %1; cvt.u32.u64 %0, t; }"
        : "=r"(a) : "l"(p));
    return a;
}
__device__ __host__ __forceinline__ uint32_t swz128(uint32_t off) {
    return off ^ ((off >> 3) & 0x70);
}
__device__ __forceinline__ void cpasync16(uint32_t d, const void* s) {
    asm volatile("cp.async.cg.shared.global [%0], [%1], 16;" :: "r"(d), "l"(s));
}
#define CP_COMMIT() asm volatile("cp.async.commit_group;" ::: "memory")
#define CP_WAIT(N)  asm volatile("cp.async.wait_group " #N ";" ::: "memory")

#define LDSM4(R, ADDR) \
    asm volatile("ldmatrix.sync.aligned.m8n8.x4.shared.b16 {%0,%1,%2,%3}, [%4];" \
        : "=r"((R)[0]), "=r"((R)[1]), "=r"((R)[2]), "=r"((R)[3]) : "r"(ADDR))

#define MMA16816(C, A, Bv) \
    asm volatile("mma.sync.aligned.m16n8k16.row.col.f32.f16.f16.f32 " \
        "{%0,%1,%2,%3}, {%4,%5,%6,%7}, {%8,%9}, {%0,%1,%2,%3};" \
        : "+f"((C)[0]), "+f"((C)[1]), "+f"((C)[2]), "+f"((C)[3]) \
        : "r"((A)[0]), "r"((A)[1]), "r"((A)[2]), "r"((A)[3]), \
          "r"((Bv)[0]), "r"((Bv)[1]))

__device__ __forceinline__ uint32_t pack2h(float a, float b) {
    __half2 h = __floats2half2_rn(a, b);
    return *(uint32_t*)&h;
}

// Stage size: [A 16K][B 16K]
#define STG 32768u
#define GEMM_SMEM 98304   // 3 stages

// ---------------------------------------------------------------------------
// Convert ALL weights in one launch. grid (16, 8, 6)
// ---------------------------------------------------------------------------
__global__ __launch_bounds__(256) void conv_w_all(
    const float* __restrict__ Wq, const float* __restrict__ Wk,
    const float* __restrict__ Wv, const float* __restrict__ Wr,
    const float* __restrict__ W1, const float* __restrict__ W2,
    __half* __restrict__ hf)
{
    int widx = blockIdx.z;
    const float* src;
    __half* dstb;
    int K, MT;
    switch (widx) {
        case 0: src = Wq; dstb = hf + OFF_WQ; K = 512;  MT = 4; break;
        case 1: src = Wk; dstb = hf + OFF_WK; K = 512;  MT = 4; break;
        case 2: src = Wv; dstb = hf + OFF_WV; K = 512;  MT = 4; break;
        case 3: src = Wr; dstb = hf + OFF_WR; K = 512;  MT = 4; break;
        case 4: src = W1; dstb = hf + OFF_W1; K = 512;  MT = 8; break;
        default: src = W2; dstb = hf + OFF_W2; K = 1024; MT = 4; break;
    }
    int NC = K >> 6;
    int kc = blockIdx.x, mt = blockIdx.y;
    if (kc >= NC || mt >= MT) return;
    char* db = (char*)(dstb + ((size_t)(mt * NC + kc)) * 8192);
    const float* sb = src + ((size_t)mt * 128) * K + kc * 64;
    for (int it = 0; it < 4; it++) {
        int u = threadIdx.x + 256 * it;
        int r = u >> 3, g = u & 7;
        float x0[8];
        #pragma unroll
        for (int q = 0; q < 2; q++) {
            float4 v = *(const float4*)(sb + (size_t)r * K + g * 8 + q * 4);
            x0[q*4+0]=v.x; x0[q*4+1]=v.y; x0[q*4+2]=v.z; x0[q*4+3]=v.w;
        }
        uint4 w;
        w.x = pack2h(x0[0], x0[1]);
        w.y = pack2h(x0[2], x0[3]);
        w.z = pack2h(x0[4], x0[5]);
        w.w = pack2h(x0[6], x0[7]);
        uint32_t sw = swz128((uint32_t)r * 128 + g * 16);
        *(uint4*)(db + sw) = w;
    }
}

// ---------------------------------------------------------------------------
// Convert+transpose z1 and z2 in one launch: grid (8, 16, 16)
// ---------------------------------------------------------------------------
__global__ __launch_bounds__(256) void conv_x2(
    const float* __restrict__ src1, const float* __restrict__ src2,
    __half* __restrict__ dst1, __half* __restrict__ dst2)
{
    const int K = 512;
    int kc = blockIdx.x, lt = blockIdx.y;
    int b = blockIdx.z & 7;
    const float* src = (blockIdx.z < 8) ? src1 : src2;
    __half* dstb = (blockIdx.z < 8) ? dst1 : dst2;
    int NC = K >> 6;
    __shared__ float sm[32][264];
    const float* sb = src + ((size_t)b * K + kc * 64) * Ln + (size_t)lt * 256;
    char* db = (char*)(dstb + (((size_t)b * 16 + lt) * NC + kc) * 16384);
    int t = threadIdx.x;
    for (int p = 0; p < 2; p++) {
        __syncthreads();
        #pragma unroll
        for (int i = 0; i < 8; i++) {
            int u = t + 256 * i;
            int kr = u >> 6;
            int lc = u & 63;
            float4 v = *(const float4*)(sb + ((size_t)(p * 32 + kr)) * Ln + lc * 4);
            sm[kr][lc*4+0]=v.x; sm[kr][lc*4+1]=v.y; sm[kr][lc*4+2]=v.z; sm[kr][lc*4+3]=v.w;
        }
        __syncthreads();
        #pragma unroll
        for (int g = 0; g < 4; g++) {
            float x0[8];
            #pragma unroll
            for (int j = 0; j < 8; j++) x0[j] = sm[g*8+j][t];
            uint4 w;
            w.x = pack2h(x0[0], x0[1]);
            w.y = pack2h(x0[2], x0[3]);
            w.z = pack2h(x0[4], x0[5]);
            w.w = pack2h(x0[6], x0[7]);
            uint32_t sw = swz128((uint32_t)t * 128 + (p * 32 + g * 8) * 2);
            *(uint4*)(db + sw) = w;
        }
    }
}

// ---------------------------------------------------------------------------
// Shared GEMM mainloop pieces (macro to keep identical codegen in 2 kernels)
// 256 threads, 8 warps of 64x32, CTA tile 128(m)x128(l), 3-stage cp.async.
// ---------------------------------------------------------------------------
#define GEMM_PROLOGUE() \
    uint32_t sbase = smem_u32(smem); \
    int tid = threadIdx.x, wid = tid >> 5, lane = tid & 31; \
    int wm = wid >> 2, wn = wid & 3; \
    int sub = lane >> 3, r = lane & 7; \
    uint32_t aRow[4], aMask[4]; \
    int kaddA = (sub >> 1) * 16; \
    _Pragma("unroll") \
    for (int i = 0; i < 4; i++) { \
        uint32_t row = wm * 64 + i * 16 + (sub & 1) * 8 + r; \
        aRow[i] = row * 128; \
        aMask[i] = (aRow[i] >> 3) & 0x70; \
    } \
    uint32_t bRow[2], bMask[2]; \
    int kaddB = (sub & 1) * 16; \
    _Pragma("unroll") \
    for (int j = 0; j < 2; j++) { \
        uint32_t row = wn * 32 + j * 16 + (sub >> 1) * 8 + r; \
        bRow[j] = row * 128; \
        bMask[j] = (bRow[j] >> 3) & 0x70; \
    } \
    float acc[4][4][4]; \
    _Pragma("unroll") \
    for (int i = 0; i < 4; i++) \
        _Pragma("unroll") \
        for (int j = 0; j < 4; j++) \
            _Pragma("unroll") \
            for (int q = 0; q < 4; q++) acc[i][j][q] = 0.f;

#define GEMM_LOAD_STAGE(kc, s) do { \
    uint32_t S = sbase + (uint32_t)(s) * STG; \
    const char* ah = Abase + (size_t)(kc) * 16384; \
    const char* bh = Bbase + (size_t)(kc) * 32768; \
    _Pragma("unroll") \
    for (int q = 0; q < 4; q++) { \
        uint32_t off = (uint32_t)tid * 64 + q * 16; \
        cpasync16(S + off,         ah + off); \
        cpasync16(S + 16384 + off, bh + off); \
    } \
} while (0)

#define GEMM_MAINLOOP(NC) \
    GEMM_LOAD_STAGE(0, 0); CP_COMMIT(); \
    if ((NC) > 1) { GEMM_LOAD_STAGE(1, 1); CP_COMMIT(); } \
    int sc = 0; \
    for (int c = 0; c < (NC); c++) { \
        CP_WAIT(1); \
        __syncthreads(); \
        if (c + 2 < (NC)) { \
            int s2 = sc + 2; if (s2 >= 3) s2 -= 3; \
            GEMM_LOAD_STAGE(c + 2, s2); CP_COMMIT(); \
        } \
        uint32_t S = sbase + (uint32_t)sc * STG; \
        _Pragma("unroll") \
        for (int kk = 0; kk < 4; kk++) { \
            int kb = kk * 32; \
            uint32_t aa[16], bb[8]; \
            _Pragma("unroll") \
            for (int i = 0; i < 4; i++) \
                LDSM4(&aa[i * 4], S + aRow[i] + (uint32_t)((kaddA + kb) ^ aMask[i])); \
            _Pragma("unroll") \
            for (int j = 0; j < 2; j++) \
                LDSM4(&bb[j * 4], S + 16384 + bRow[j] + (uint32_t)((kaddB + kb) ^ bMask[j])); \
            _Pragma("unroll") \
            for (int mi = 0; mi < 4; mi++) \
                _Pragma("unroll") \
                for (int nj = 0; nj < 4; nj++) \
                    MMA16816(acc[mi][nj], &aa[mi * 4], &bb[nj * 2]); \
        } \
        sc++; if (sc == 3) sc = 0; \
    }

// ---------------------------------------------------------------------------
// Merged Q/K/V projection GEMM: grid (4, 32, 24); z>>3 selects {Q,K,V}.
// M=K=512, fp32 out, no residual, no act.
// ---------------------------------------------------------------------------
__global__ __launch_bounds__(256, 2) void gemm_qkv(
    const __half* __restrict__ hf,
    const float* __restrict__ bq, const float* __restrict__ bk,
    const float* __restrict__ bv,
    float* __restrict__ qo, float* __restrict__ ko, float* __restrict__ vo)
{
    extern __shared__ __align__(1024) char smem[];
    const int NC = 8;
    int mt = blockIdx.x, lt = blockIdx.y;
    int which = blockIdx.z >> 3, b = blockIdx.z & 7;

    const __half* Wc = (which == 0) ? hf + OFF_WQ : (which == 1) ? hf + OFF_WK : hf + OFF_WV;
    const float* bias = (which == 0) ? bq : (which == 1) ? bk : bv;
    const __half* Xc = (which == 0) ? hf + OFF_Z1C : hf + OFF_Z2C;
    float* Out = (which == 0) ? qo : (which == 1) ? ko : vo;

    const char* Abase = (const char*)Wc + ((size_t)mt * NC) * 16384;
    int lt256 = lt >> 1, half = lt & 1;
    const char* Bbase = (const char*)Xc + (((size_t)b * 16 + lt256) * NC) * 32768
                        + (size_t)half * 16384;

    GEMM_PROLOGUE();
    GEMM_MAINLOOP(NC);

    int g = lane >> 2, tg = lane & 3;
    #pragma unroll
    for (int mi = 0; mi < 4; mi++) {
        #pragma unroll
        for (int h2 = 0; h2 < 2; h2++) {
            int m = mt * 128 + wm * 64 + mi * 16 + h2 * 8 + g;
            float bi = bias[m];
            size_t rowoff = ((size_t)b * 512 + m) * Ln + (size_t)lt * 128 + wn * 32;
            #pragma unroll
            for (int nj = 0; nj < 4; nj++) {
                int col = nj * 8 + 2 * tg;
                float v0 = acc[mi][nj][h2 * 2 + 0] + bi;
                float v1 = acc[mi][nj][h2 * 2 + 1] + bi;
                *(float2*)(Out + rowoff + col) = make_float2(v0, v1);
            }
        }
    }
}

// ---------------------------------------------------------------------------
// General GEMM. outmode 0: fp32 Out (+Res)(+ELU). outmode 1: fp16 tiled Outh.
// ---------------------------------------------------------------------------
__global__ __launch_bounds__(256, 2) void gemm_wm(
    const __half* __restrict__ Wc, const float* __restrict__ bias,
    const __half* __restrict__ Xc, float* __restrict__ Out,
    __half* __restrict__ Outh,
    const float* __restrict__ Res, int M, int K, int act, int outmode)
{
    extern __shared__ __align__(1024) char smem[];
    const int NC = K >> 6;
    int mt = blockIdx.x, lt = blockIdx.y, b = blockIdx.z;

    const char* Abase = (const char*)Wc + ((size_t)mt * NC) * 16384;
    int lt256 = lt >> 1, half = lt & 1;
    const char* Bbase = (const char*)Xc + (((size_t)b * 16 + lt256) * NC) * 32768
                        + (size_t)half * 16384;

    GEMM_PROLOGUE();
    GEMM_MAINLOOP(NC);

    int g = lane >> 2, tg = lane & 3;

    if (outmode == 0) {
        #pragma unroll
        for (int mi = 0; mi < 4; mi++) {
            #pragma unroll
            for (int h2 = 0; h2 < 2; h2++) {
                int m = mt * 128 + wm * 64 + mi * 16 + h2 * 8 + g;
                float bi = bias[m];
                size_t rowoff = ((size_t)b * M + m) * Ln + (size_t)lt * 128 + wn * 32;
                #pragma unroll
                for (int nj = 0; nj < 4; nj++) {
                    int col = nj * 8 + 2 * tg;
                    float v0 = acc[mi][nj][h2 * 2 + 0] + bi;
                    float v1 = acc[mi][nj][h2 * 2 + 1] + bi;
                    if (Res) {
                        float2 r2 = *(const float2*)(Res + rowoff + col);
                        v0 += r2.x; v1 += r2.y;
                    }
                    if (act) {
                        v0 = v0 > 0.f ? v0 : expm1f(v0);
                        v1 = v1 > 0.f ? v1 : expm1f(v1);
                    }
                    *(float2*)(Out + rowoff + col) = make_float2(v0, v1);
                }
            }
        }
    } else {
        __syncthreads();
        __half* smh = (__half*)smem;
        #pragma unroll
        for (int mi = 0; mi < 4; mi++) {
            #pragma unroll
            for (int h2 = 0; h2 < 2; h2++) {
                int ml = wm * 64 + mi * 16 + h2 * 8 + g;
                float bi = bias[mt * 128 + ml];
                #pragma unroll
                for (int nj = 0; nj < 4; nj++) {
                    int ll = wn * 32 + nj * 8 + 2 * tg;
                    float v0 = acc[mi][nj][h2 * 2 + 0] + bi;
                    float v1 = acc[mi][nj][h2 * 2 + 1] + bi;
                    if (act) {
                        v0 = v0 > 0.f ? v0 : expm1f(v0);
                        v1 = v1 > 0.f ? v1 : expm1f(v1);
                    }
                    smh[(uint32_t)ll * 136 + ml]       = __float2half(v0);
                    smh[(uint32_t)(ll + 1) * 136 + ml] = __float2half(v1);
                }
            }
        }
        __syncthreads();
        int rowbase = (lt & 1) * 128;
        int NCo = M >> 6;
        #pragma unroll
        for (int kc = 0; kc < 2; kc++) {
            char* db = (char*)(Outh + (((size_t)b * 16 + lt256) * NCo + (mt * 2 + kc)) * 16384);
            #pragma unroll
            for (int it = 0; it < 4; it++) {
                int u = tid + 256 * it;
                int row = u >> 3, j = u & 7;
                uint4 w = *(uint4*)&smh[(uint32_t)row * 136 + kc * 64 + j * 8];
                *(uint4*)(db + swz128((uint32_t)(rowbase + row) * 128 + j * 16)) = w;
            }
        }
    }
}

// ---------------------------------------------------------------------------
// Softmax over length
// ---------------------------------------------------------------------------
__global__ __launch_bounds__(256) void softmax_len(float* __restrict__ data)
{
    __shared__ float red[256];
    float* p = data + (size_t)blockIdx.x * Ln;
    int t = threadIdx.x;
    float v[16];
    float m = -1e30f;
    #pragma unroll
    for (int i = 0; i < 16; i++) { v[i] = p[t + 256 * i]; m = fmaxf(m, v[i]); }
    red[t] = m; __syncthreads();
    for (int off = 128; off > 0; off >>= 1) {
        if (t < off) red[t] = fmaxf(red[t], red[t + off]);
        __syncthreads();
    }
    m = red[0];
    __syncthreads();
    float s = 0.f;
    #pragma unroll
    for (int i = 0; i < 16; i++) { v[i] = __expf(v[i] - m); s += v[i]; }
    red[t] = s; __syncthreads();
    for (int off = 128; off > 0; off >>= 1) {
        if (t < off) red[t] += red[t + off];
        __syncthreads();
    }
    float inv = 1.f / red[0];
    #pragma unroll
    for (int i = 0; i < 16; i++) p[t + 256 * i] = v[i] * inv;
}

// ---------------------------------------------------------------------------
// ctx partials
// ---------------------------------------------------------------------------
__global__ __launch_bounds__(256) void ctx_kernel(
    const float* __restrict__ kk, const float* __restrict__ vv,
    float* __restrict__ ctxp)
{
    int bh = blockIdx.x;
    int sp = blockIdx.y;
    const float* kb = kk + (size_t)bh * Dh * Ln;
    const float* vb = vv + (size_t)bh * Dh * Ln;

    __shared__ float ks[64][33];
    __shared__ float vs[64][33];

    int tid = threadIdx.x;
    int lt = tid & 31, dr = tid >> 5;
    int tx = tid & 15, ty = tid >> 4;

    float acc[4][4];
    #pragma unroll
    for (int i = 0; i < 4; i++)
        #pragma unroll
        for (int j = 0; j < 4; j++) acc[i][j] = 0.f;

    int lbeg = sp * (Ln / NSPLIT);
    int lend = lbeg + (Ln / NSPLIT);
    for (int l0 = lbeg; l0 < lend; l0 += 32) {
        __syncthreads();
        #pragma unroll
        for (int r = 0; r < 8; r++) {
            int dk = dr + 8 * r;
            ks[dk][lt] = kb[(size_t)dk * Ln + l0 + lt];
            vs[dk][lt] = vb[(size_t)dk * Ln + l0 + lt];
        }
        __syncthreads();
        #pragma unroll
        for (int l2 = 0; l2 < 32; l2++) {
            float av[4], bw[4];
            #pragma unroll
            for (int i = 0; i < 4; i++) av[i] = ks[ty * 4 + i][l2];
            #pragma unroll
            for (int j = 0; j < 4; j++) bw[j] = vs[tx * 4 + j][l2];
            #pragma unroll
            for (int i = 0; i < 4; i++)
                #pragma unroll
                for (int j = 0; j < 4; j++)
                    acc[i][j] += av[i] * bw[j];
        }
    }
    #pragma unroll
    for (int i = 0; i < 4; i++)
        #pragma unroll
        for (int j = 0; j < 4; j++) {
            int dk = ty * 4 + i, dv = tx * 4 + j;
            ctxp[(((size_t)sp * 64 + bh) * 64 + dk) * 64 + dv] = acc[i][j];
        }
}

// ---------------------------------------------------------------------------
// att fused: head-softmax(q) inline + ctx^T apply + fp16 tiled output
// ---------------------------------------------------------------------------
__global__ __launch_bounds__(256) void att_fused(
    const float* __restrict__ ctxp, const float* __restrict__ q,
    __half* __restrict__ attc)
{
    int bh = blockIdx.y;
    int b = bh >> 3, h = bh & 7;
    __shared__ float cs[64][64];
    int tid = threadIdx.x;

    float4* cs4 = (float4*)cs;
    #pragma unroll
    for (int r = 0; r < 4; r++) {
        int idx = tid + 256 * r;
        float4 sum = make_float4(0.f, 0.f, 0.f, 0.f);
        #pragma unroll
        for (int s = 0; s < NSPLIT; s++) {
            const float4* p = (const float4*)(ctxp + ((size_t)s * 64 + bh) * 4096);
            float4 t = p[idx];
            sum.x += t.x; sum.y += t.y; sum.z += t.z; sum.w += t.w;
        }
        cs4[idx] = sum;
    }
    __syncthreads();

    int l = blockIdx.x * 256 + tid;
    const float* qb = q + (size_t)bh * Dh * Ln + l;

    float qv[64];
    float mx = -1e30f;
    #pragma unroll
    for (int d = 0; d < 64; d++) { qv[d] = qb[(size_t)d * Ln]; mx = fmaxf(mx, qv[d]); }
    float s = 0.f;
    #pragma unroll
    for (int d = 0; d < 64; d++) { qv[d] = __expf(qv[d] - mx); s += qv[d]; }
    float inv = 1.f / s;

    float acc[64];
    #pragma unroll
    for (int d = 0; d < 64; d++) acc[d] = 0.f;

    #pragma unroll 4
    for (int dk = 0; dk < 64; dk++) {
        float qq = qv[dk] * inv;
        #pragma unroll
        for (int j = 0; j < 16; j++) {
            float4 c4 = *(const float4*)&cs[dk][j * 4];
            acc[4 * j + 0] += c4.x * qq;
            acc[4 * j + 1] += c4.y * qq;
            acc[4 * j + 2] += c4.z * qq;
            acc[4 * j + 3] += c4.w * qq;
        }
    }

    char* db = (char*)(attc + (((size_t)b * 16 + blockIdx.x) * 8 + h) * 16384);
    #pragma unroll
    for (int j = 0; j < 8; j++) {
        uint4 w;
        w.x = pack2h(acc[8*j+0], acc[8*j+1]);
        w.y = pack2h(acc[8*j+2], acc[8*j+3]);
        w.z = pack2h(acc[8*j+4], acc[8*j+5]);
        w.w = pack2h(acc[8*j+6], acc[8*j+7]);
        *(uint4*)(db + swz128((uint32_t)tid * 128 + j * 16)) = w;
    }
}

// ---------------------------------------------------------------------------
// Channel LayerNorm over C=512 -> fp32 out
// ---------------------------------------------------------------------------
__global__ __launch_bounds__(256) void ln_kernel(
    const float* __restrict__ in, float* __restrict__ out,
    const float* __restrict__ g, const float* __restrict__ be)
{
    __shared__ float ss[8][32], sq[8][32], smean[32], srstd[32];
    int blk = blockIdx.x;
    int b = blk >> 7;
    int li = threadIdx.x & 31;
    int l = ((blk & 127) << 5) + li;
    int r = threadIdx.x >> 5;
    const float* base = in + (size_t)b * Cc * Ln + l;

    float s = 0.f, s2 = 0.f;
    #pragma unroll
    for (int k2 = 0; k2 < 64; k2++) {
        int c = r * 64 + k2;
        float x = base[(size_t)c * Ln];
        s += x; s2 += x * x;
    }
    ss[r][li] = s; sq[r][li] = s2;
    __syncthreads();
    if (r == 0) {
        float ts = ss[0][li], t2 = sq[0][li];
        #pragma unroll
        for (int rr = 1; rr < 8; rr++) { ts += ss[rr][li]; t2 += sq[rr][li]; }
        float mean = ts * (1.f / 512.f);
        float var = t2 * (1.f / 512.f) - mean * mean;
        smean[li] = mean;
        srstd[li] = rsqrtf(var + 1e-5f);
    }
    __syncthreads();
    float mean = smean[li], rstd = srstd[li];
    float* ob = out + (size_t)b * Cc * Ln + l;
    #pragma unroll
    for (int k2 = 0; k2 < 64; k2++) {
        int c = r * 64 + k2;
        float x = base[(size_t)c * Ln];
        ob[(size_t)c * Ln] = (x - mean) * rstd * g[c] + be[c];
    }
}

// ---------------------------------------------------------------------------
// Channel LayerNorm -> fp16 tiled out
// ---------------------------------------------------------------------------
__global__ __launch_bounds__(256) void ln_h(
    const float* __restrict__ in, __half* __restrict__ outc,
    const float* __restrict__ g, const float* __restrict__ be)
{
    __shared__ float ss[8][32], sq[8][32], smean[32], srstd[32];
    int blk = blockIdx.x;
    int b = blk >> 7;
    int li = threadIdx.x & 31;
    int l = ((blk & 127) << 5) + li;
    int r = threadIdx.x >> 5;
    const float* base = in + (size_t)b * Cc * Ln + l;

    float s = 0.f, s2 = 0.f;
    float x0[64];
    #pragma unroll
    for (int k2 = 0; k2 < 64; k2++) {
        int c = r * 64 + k2;
        float x = base[(size_t)c * Ln];
        x0[k2] = x;
        s += x; s2 += x * x;
    }
    ss[r][li] = s; sq[r][li] = s2;
    __syncthreads();
    if (r == 0) {
        float ts = ss[0][li], t2 = sq[0][li];
        #pragma unroll
        for (int rr = 1; rr < 8; rr++) { ts += ss[rr][li]; t2 += sq[rr][li]; }
        float mean = ts * (1.f / 512.f);
        float var = t2 * (1.f / 512.f) - mean * mean;
        smean[li] = mean;
        srstd[li] = rsqrtf(var + 1e-5f);
    }
    __syncthreads();
    float mean = smean[li], rstd = srstd[li];

    char* db = (char*)(outc + (((size_t)b * 16 + (l >> 8)) * 8 + r) * 16384);
    uint32_t row = (uint32_t)(l & 255);
    #pragma unroll
    for (int j = 0; j < 8; j++) {
        float v[8];
        #pragma unroll
        for (int q2 = 0; q2 < 8; q2++) {
            int c = r * 64 + j * 8 + q2;
            v[q2] = (x0[j * 8 + q2] - mean) * rstd * g[c] + be[c];
        }
        uint4 w;
        w.x = pack2h(v[0], v[1]);
        w.y = pack2h(v[2], v[3]);
        w.z = pack2h(v[4], v[5]);
        w.w = pack2h(v[6], v[7]);
        *(uint4*)(db + swz128(row * 128 + j * 16)) = w;
    }
}

// ---------------------------------------------------------------------------
extern "C" void kernel_launch(void* const* d_in, const int* in_sizes, int n_in,
                              void* d_out, int out_size)
{
    const float* z1  = (const float*)d_in[0];
    const float* z2  = (const float*)d_in[1];
    const float* Wq  = (const float*)d_in[2];
    const float* bq  = (const float*)d_in[3];
    const float* Wk  = (const float*)d_in[4];
    const float* bkb = (const float*)d_in[5];
    const float* Wv  = (const float*)d_in[6];
    const float* bv  = (const float*)d_in[7];
    const float* Wr  = (const float*)d_in[8];
    const float* br  = (const float*)d_in[9];
    const float* g1  = (const float*)d_in[10];
    const float* be1 = (const float*)d_in[11];
    const float* W1  = (const float*)d_in[12];
    const float* b1  = (const float*)d_in[13];
    const float* W2  = (const float*)d_in[14];
    const float* b2  = (const float*)d_in[15];
    const float* g2  = (const float*)d_in[16];
    const float* be2 = (const float*)d_in[17];

    float* fs = nullptr;
    cudaGetSymbolAddress((void**)&fs, g_scratch);
    __half* hf = nullptr;
    cudaGetSymbolAddress((void**)&hf, g_hf);

    const size_t SZ = (size_t)Bn * Cc * Ln;   // 16777216
    float* q    = fs;
    float* k    = fs + SZ;
    float* v    = fs + 2 * SZ;
    float* z    = fs + 4 * SZ;
    float* y    = fs + 5 * SZ;
    float* ctxp = fs + 8 * SZ;

    cudaFuncSetAttribute(gemm_wm, cudaFuncAttributeMaxDynamicSharedMemorySize, GEMM_SMEM);
    cudaFuncSetAttribute(gemm_qkv, cudaFuncAttributeMaxDynamicSharedMemorySize, GEMM_SMEM);

    dim3 thr(256);
    conv_w_all<<<dim3(16, 8, 6), thr>>>(Wq, Wk, Wv, Wr, W1, W2, hf);
    conv_x2<<<dim3(8, 16, 16), thr>>>(z1, z2, hf + OFF_Z1C, hf + OFF_Z2C);

    // Merged Q/K/V projections
    gemm_qkv<<<dim3(4, 32, 24), thr, GEMM_SMEM>>>(hf, bq, bkb, bv, q, k, v);

    // key softmax over length
    softmax_len<<<Bn * Cc, thr>>>(k);

    // Attention core
    ctx_kernel<<<dim3(Bn * Hh, NSPLIT), thr>>>(k, v, ctxp);
    att_fused<<<dim3(Ln / 256, Bn * Hh), thr>>>(ctxp, q, hf + OFF_ATTC);

    // Reprojection + residual (fp32 out)
    gemm_wm<<<dim3(4, 32, 8), thr, GEMM_SMEM>>>(hf + OFF_WR, br, hf + OFF_ATTC, z, nullptr, z1, 512, 512, 0, 0);

    // LN1 -> fp16 tiled
    ln_h<<<Bn * (Ln / 32), thr>>>(z, hf + OFF_ZC, g1, be1);

    // FFN1 -> fp16 tiled h (ELU fused), FFN2 -> fp32 y
    gemm_wm<<<dim3(8, 32, 8), thr, GEMM_SMEM>>>(hf + OFF_W1, b1, hf + OFF_ZC, nullptr, hf + OFF_HC, nullptr, 1024, 512, 1, 1);
    gemm_wm<<<dim3(4, 32, 8), thr, GEMM_SMEM>>>(hf + OFF_W2, b2, hf + OFF_HC, y, nullptr, nullptr, 512, 1024, 0, 0);

    // LN2 -> output
    ln_kernel<<<Bn * (Ln / 32), thr>>>(y, (float*)d_out, g2, be2);
}

// round 9
// speedup vs baseline: 1.3474x; 1.0209x over previous
#include <cuda_runtime.h>
#include <cuda_fp16.h>
#include <cstdint>

// Problem constants
#define Bn  8
#define Cc  512
#define Ln  4096
#define Hh  8
#define Dh  64
#define NSPLIT 4

// ---------------------------------------------------------------------------
// Scratch
// ---------------------------------------------------------------------------
__device__ float g_scratch[135266304];
__device__ __half g_hf[102760448];

// half-element offsets into g_hf
#define OFF_Z1C  0ull
#define OFF_Z2C  16777216ull
#define OFF_ATTC 33554432ull
#define OFF_ZC   50331648ull
#define OFF_HC   67108864ull
#define OFF_WQ   100663296ull
#define OFF_WK   100925440ull
#define OFF_WV   101187584ull
#define OFF_WR   101449728ull
#define OFF_W1   101711872ull
#define OFF_W2   102236160ull

// ---------------------------------------------------------------------------
// Helpers
// ---------------------------------------------------------------------------
__device__ __forceinline__ uint32_t smem_u32(const void* p) {
    uint32_t a;
    asm("{ .reg .u64 t; cvta.to.shared.u64 t, %1; cvt.u32.u64 %0, t; }"
        : "=r"(a) : "l"(p));
    return a;
}
__device__ __host__ __forceinline__ uint32_t swz128(uint32_t off) {
    return off ^ ((off >> 3) & 0x70);
}
__device__ __forceinline__ void cpasync16(uint32_t d, const void* s) {
    asm volatile("cp.async.cg.shared.global [%0], [%1], 16;" :: "r"(d), "l"(s));
}
#define CP_COMMIT() asm volatile("cp.async.commit_group;" ::: "memory")
#define CP_WAIT(N)  asm volatile("cp.async.wait_group " #N ";" ::: "memory")

#define LDSM4(R, ADDR) \
    asm volatile("ldmatrix.sync.aligned.m8n8.x4.shared.b16 {%0,%1,%2,%3}, [%4];" \
        : "=r"((R)[0]), "=r"((R)[1]), "=r"((R)[2]), "=r"((R)[3]) : "r"(ADDR))

#define MMA16816(C, A, Bv) \
    asm volatile("mma.sync.aligned.m16n8k16.row.col.f32.f16.f16.f32 " \
        "{%0,%1,%2,%3}, {%4,%5,%6,%7}, {%8,%9}, {%0,%1,%2,%3};" \
        : "+f"((C)[0]), "+f"((C)[1]), "+f"((C)[2]), "+f"((C)[3]) \
        : "r"((A)[0]), "r"((A)[1]), "r"((A)[2]), "r"((A)[3]), \
          "r"((Bv)[0]), "r"((Bv)[1]))

__device__ __forceinline__ uint32_t pack2h(float a, float b) {
    __half2 h = __floats2half2_rn(a, b);
    return *(uint32_t*)&h;
}

#define STG 32768u
#define GEMM_SMEM 98304   // 3 stages

// ---------------------------------------------------------------------------
// Convert ALL weights in one launch. grid (16, 8, 6)
// ---------------------------------------------------------------------------
__global__ __launch_bounds__(256) void conv_w_all(
    const float* __restrict__ Wq, const float* __restrict__ Wk,
    const float* __restrict__ Wv, const float* __restrict__ Wr,
    const float* __restrict__ W1, const float* __restrict__ W2,
    __half* __restrict__ hf)
{
    int widx = blockIdx.z;
    const float* src;
    __half* dstb;
    int K, MT;
    switch (widx) {
        case 0: src = Wq; dstb = hf + OFF_WQ; K = 512;  MT = 4; break;
        case 1: src = Wk; dstb = hf + OFF_WK; K = 512;  MT = 4; break;
        case 2: src = Wv; dstb = hf + OFF_WV; K = 512;  MT = 4; break;
        case 3: src = Wr; dstb = hf + OFF_WR; K = 512;  MT = 4; break;
        case 4: src = W1; dstb = hf + OFF_W1; K = 512;  MT = 8; break;
        default: src = W2; dstb = hf + OFF_W2; K = 1024; MT = 4; break;
    }
    int NC = K >> 6;
    int kc = blockIdx.x, mt = blockIdx.y;
    if (kc >= NC || mt >= MT) return;
    char* db = (char*)(dstb + ((size_t)(mt * NC + kc)) * 8192);
    const float* sb = src + ((size_t)mt * 128) * K + kc * 64;
    for (int it = 0; it < 4; it++) {
        int u = threadIdx.x + 256 * it;
        int r = u >> 3, g = u & 7;
        float x0[8];
        #pragma unroll
        for (int q = 0; q < 2; q++) {
            float4 v = *(const float4*)(sb + (size_t)r * K + g * 8 + q * 4);
            x0[q*4+0]=v.x; x0[q*4+1]=v.y; x0[q*4+2]=v.z; x0[q*4+3]=v.w;
        }
        uint4 w;
        w.x = pack2h(x0[0], x0[1]);
        w.y = pack2h(x0[2], x0[3]);
        w.z = pack2h(x0[4], x0[5]);
        w.w = pack2h(x0[6], x0[7]);
        uint32_t sw = swz128((uint32_t)r * 128 + g * 16);
        *(uint4*)(db + sw) = w;
    }
}

// ---------------------------------------------------------------------------
// Convert+transpose z1 and z2 in one launch: grid (8, 16, 16)
// ---------------------------------------------------------------------------
__global__ __launch_bounds__(256) void conv_x2(
    const float* __restrict__ src1, const float* __restrict__ src2,
    __half* __restrict__ dst1, __half* __restrict__ dst2)
{
    const int K = 512;
    int kc = blockIdx.x, lt = blockIdx.y;
    int b = blockIdx.z & 7;
    const float* src = (blockIdx.z < 8) ? src1 : src2;
    __half* dstb = (blockIdx.z < 8) ? dst1 : dst2;
    int NC = K >> 6;
    __shared__ float sm[32][264];
    const float* sb = src + ((size_t)b * K + kc * 64) * Ln + (size_t)lt * 256;
    char* db = (char*)(dstb + (((size_t)b * 16 + lt) * NC + kc) * 16384);
    int t = threadIdx.x;
    for (int p = 0; p < 2; p++) {
        __syncthreads();
        #pragma unroll
        for (int i = 0; i < 8; i++) {
            int u = t + 256 * i;
            int kr = u >> 6;
            int lc = u & 63;
            float4 v = *(const float4*)(sb + ((size_t)(p * 32 + kr)) * Ln + lc * 4);
            sm[kr][lc*4+0]=v.x; sm[kr][lc*4+1]=v.y; sm[kr][lc*4+2]=v.z; sm[kr][lc*4+3]=v.w;
        }
        __syncthreads();
        #pragma unroll
        for (int g = 0; g < 4; g++) {
            float x0[8];
            #pragma unroll
            for (int j = 0; j < 8; j++) x0[j] = sm[g*8+j][t];
            uint4 w;
            w.x = pack2h(x0[0], x0[1]);
            w.y = pack2h(x0[2], x0[3]);
            w.z = pack2h(x0[4], x0[5]);
            w.w = pack2h(x0[6], x0[7]);
            uint32_t sw = swz128((uint32_t)t * 128 + (p * 32 + g * 8) * 2);
            *(uint4*)(db + sw) = w;
        }
    }
}

// ---------------------------------------------------------------------------
// Shared GEMM mainloop (256 threads, 8 warps 64x32, 128x128 tile, 3 stages)
// ---------------------------------------------------------------------------
#define GEMM_PROLOGUE() \
    uint32_t sbase = smem_u32(smem); \
    int tid = threadIdx.x, wid = tid >> 5, lane = tid & 31; \
    int wm = wid >> 2, wn = wid & 3; \
    int sub = lane >> 3, r = lane & 7; \
    uint32_t aRow[4], aMask[4]; \
    int kaddA = (sub >> 1) * 16; \
    _Pragma("unroll") \
    for (int i = 0; i < 4; i++) { \
        uint32_t row = wm * 64 + i * 16 + (sub & 1) * 8 + r; \
        aRow[i] = row * 128; \
        aMask[i] = (aRow[i] >> 3) & 0x70; \
    } \
    uint32_t bRow[2], bMask[2]; \
    int kaddB = (sub & 1) * 16; \
    _Pragma("unroll") \
    for (int j = 0; j < 2; j++) { \
        uint32_t row = wn * 32 + j * 16 + (sub >> 1) * 8 + r; \
        bRow[j] = row * 128; \
        bMask[j] = (bRow[j] >> 3) & 0x70; \
    } \
    float acc[4][4][4]; \
    _Pragma("unroll") \
    for (int i = 0; i < 4; i++) \
        _Pragma("unroll") \
        for (int j = 0; j < 4; j++) \
            _Pragma("unroll") \
            for (int q = 0; q < 4; q++) acc[i][j][q] = 0.f;

#define GEMM_LOAD_STAGE(kc, s) do { \
    uint32_t S = sbase + (uint32_t)(s) * STG; \
    const char* ah = Abase + (size_t)(kc) * 16384; \
    const char* bh = Bbase + (size_t)(kc) * 32768; \
    _Pragma("unroll") \
    for (int q = 0; q < 4; q++) { \
        uint32_t off = (uint32_t)tid * 64 + q * 16; \
        cpasync16(S + off,         ah + off); \
        cpasync16(S + 16384 + off, bh + off); \
    } \
} while (0)

#define GEMM_MAINLOOP(NC) \
    GEMM_LOAD_STAGE(0, 0); CP_COMMIT(); \
    if ((NC) > 1) { GEMM_LOAD_STAGE(1, 1); CP_COMMIT(); } \
    int sc = 0; \
    for (int c = 0; c < (NC); c++) { \
        CP_WAIT(1); \
        __syncthreads(); \
        if (c + 2 < (NC)) { \
            int s2 = sc + 2; if (s2 >= 3) s2 -= 3; \
            GEMM_LOAD_STAGE(c + 2, s2); CP_COMMIT(); \
        } \
        uint32_t S = sbase + (uint32_t)sc * STG; \
        _Pragma("unroll") \
        for (int kk = 0; kk < 4; kk++) { \
            int kb = kk * 32; \
            uint32_t aa[16], bb[8]; \
            _Pragma("unroll") \
            for (int i = 0; i < 4; i++) \
                LDSM4(&aa[i * 4], S + aRow[i] + (uint32_t)((kaddA + kb) ^ aMask[i])); \
            _Pragma("unroll") \
            for (int j = 0; j < 2; j++) \
                LDSM4(&bb[j * 4], S + 16384 + bRow[j] + (uint32_t)((kaddB + kb) ^ bMask[j])); \
            _Pragma("unroll") \
            for (int mi = 0; mi < 4; mi++) \
                _Pragma("unroll") \
                for (int nj = 0; nj < 4; nj++) \
                    MMA16816(acc[mi][nj], &aa[mi * 4], &bb[nj * 2]); \
        } \
        sc++; if (sc == 3) sc = 0; \
    }

// ---------------------------------------------------------------------------
// Merged Q/K/V projection GEMM: grid (4, 32, 24); z>>3 selects {Q,K,V}.
// Q -> fp32; K,V -> fp16 flat [B, C, L].
// ---------------------------------------------------------------------------
__global__ __launch_bounds__(256, 2) void gemm_qkv(
    const __half* __restrict__ hf,
    const float* __restrict__ bq, const float* __restrict__ bk,
    const float* __restrict__ bv,
    float* __restrict__ qo, __half* __restrict__ kh, __half* __restrict__ vh)
{
    extern __shared__ __align__(1024) char smem[];
    const int NC = 8;
    int mt = blockIdx.x, lt = blockIdx.y;
    int which = blockIdx.z >> 3, b = blockIdx.z & 7;

    const __half* Wc = (which == 0) ? hf + OFF_WQ : (which == 1) ? hf + OFF_WK : hf + OFF_WV;
    const float* bias = (which == 0) ? bq : (which == 1) ? bk : bv;
    const __half* Xc = (which == 0) ? hf + OFF_Z1C : hf + OFF_Z2C;

    const char* Abase = (const char*)Wc + ((size_t)mt * NC) * 16384;
    int lt256 = lt >> 1, half = lt & 1;
    const char* Bbase = (const char*)Xc + (((size_t)b * 16 + lt256) * NC) * 32768
                        + (size_t)half * 16384;

    GEMM_PROLOGUE();
    GEMM_MAINLOOP(NC);

    int g = lane >> 2, tg = lane & 3;
    if (which == 0) {
        #pragma unroll
        for (int mi = 0; mi < 4; mi++) {
            #pragma unroll
            for (int h2 = 0; h2 < 2; h2++) {
                int m = mt * 128 + wm * 64 + mi * 16 + h2 * 8 + g;
                float bi = bias[m];
                size_t rowoff = ((size_t)b * 512 + m) * Ln + (size_t)lt * 128 + wn * 32;
                #pragma unroll
                for (int nj = 0; nj < 4; nj++) {
                    int col = nj * 8 + 2 * tg;
                    float v0 = acc[mi][nj][h2 * 2 + 0] + bi;
                    float v1 = acc[mi][nj][h2 * 2 + 1] + bi;
                    *(float2*)(qo + rowoff + col) = make_float2(v0, v1);
                }
            }
        }
    } else {
        __half* Out = (which == 1) ? kh : vh;
        #pragma unroll
        for (int mi = 0; mi < 4; mi++) {
            #pragma unroll
            for (int h2 = 0; h2 < 2; h2++) {
                int m = mt * 128 + wm * 64 + mi * 16 + h2 * 8 + g;
                float bi = bias[m];
                size_t rowoff = ((size_t)b * 512 + m) * Ln + (size_t)lt * 128 + wn * 32;
                #pragma unroll
                for (int nj = 0; nj < 4; nj++) {
                    int col = nj * 8 + 2 * tg;
                    float v0 = acc[mi][nj][h2 * 2 + 0] + bi;
                    float v1 = acc[mi][nj][h2 * 2 + 1] + bi;
                    *(__half2*)(Out + rowoff + col) = __floats2half2_rn(v0, v1);
                }
            }
        }
    }
}

// ---------------------------------------------------------------------------
// General GEMM. outmode 0: fp32 Out (+Res)(+ELU). outmode 1: fp16 tiled Outh.
// ---------------------------------------------------------------------------
__global__ __launch_bounds__(256, 2) void gemm_wm(
    const __half* __restrict__ Wc, const float* __restrict__ bias,
    const __half* __restrict__ Xc, float* __restrict__ Out,
    __half* __restrict__ Outh,
    const float* __restrict__ Res, int M, int K, int act, int outmode)
{
    extern __shared__ __align__(1024) char smem[];
    const int NC = K >> 6;
    int mt = blockIdx.x, lt = blockIdx.y, b = blockIdx.z;

    const char* Abase = (const char*)Wc + ((size_t)mt * NC) * 16384;
    int lt256 = lt >> 1, half = lt & 1;
    const char* Bbase = (const char*)Xc + (((size_t)b * 16 + lt256) * NC) * 32768
                        + (size_t)half * 16384;

    GEMM_PROLOGUE();
    GEMM_MAINLOOP(NC);

    int g = lane >> 2, tg = lane & 3;

    if (outmode == 0) {
        #pragma unroll
        for (int mi = 0; mi < 4; mi++) {
            #pragma unroll
            for (int h2 = 0; h2 < 2; h2++) {
                int m = mt * 128 + wm * 64 + mi * 16 + h2 * 8 + g;
                float bi = bias[m];
                size_t rowoff = ((size_t)b * M + m) * Ln + (size_t)lt * 128 + wn * 32;
                #pragma unroll
                for (int nj = 0; nj < 4; nj++) {
                    int col = nj * 8 + 2 * tg;
                    float v0 = acc[mi][nj][h2 * 2 + 0] + bi;
                    float v1 = acc[mi][nj][h2 * 2 + 1] + bi;
                    if (Res) {
                        float2 r2 = *(const float2*)(Res + rowoff + col);
                        v0 += r2.x; v1 += r2.y;
                    }
                    if (act) {
                        v0 = v0 > 0.f ? v0 : expm1f(v0);
                        v1 = v1 > 0.f ? v1 : expm1f(v1);
                    }
                    *(float2*)(Out + rowoff + col) = make_float2(v0, v1);
                }
            }
        }
    } else {
        __syncthreads();
        __half* smh = (__half*)smem;
        #pragma unroll
        for (int mi = 0; mi < 4; mi++) {
            #pragma unroll
            for (int h2 = 0; h2 < 2; h2++) {
                int ml = wm * 64 + mi * 16 + h2 * 8 + g;
                float bi = bias[mt * 128 + ml];
                #pragma unroll
                for (int nj = 0; nj < 4; nj++) {
                    int ll = wn * 32 + nj * 8 + 2 * tg;
                    float v0 = acc[mi][nj][h2 * 2 + 0] + bi;
                    float v1 = acc[mi][nj][h2 * 2 + 1] + bi;
                    if (act) {
                        v0 = v0 > 0.f ? v0 : expm1f(v0);
                        v1 = v1 > 0.f ? v1 : expm1f(v1);
                    }
                    smh[(uint32_t)ll * 136 + ml]       = __float2half(v0);
                    smh[(uint32_t)(ll + 1) * 136 + ml] = __float2half(v1);
                }
            }
        }
        __syncthreads();
        int rowbase = (lt & 1) * 128;
        int NCo = M >> 6;
        #pragma unroll
        for (int kc = 0; kc < 2; kc++) {
            char* db = (char*)(Outh + (((size_t)b * 16 + lt256) * NCo + (mt * 2 + kc)) * 16384);
            #pragma unroll
            for (int it = 0; it < 4; it++) {
                int u = tid + 256 * it;
                int row = u >> 3, j = u & 7;
                uint4 w = *(uint4*)&smh[(uint32_t)row * 136 + kc * 64 + j * 8];
                *(uint4*)(db + swz128((uint32_t)(rowbase + row) * 128 + j * 16)) = w;
            }
        }
    }
}

// ---------------------------------------------------------------------------
// Softmax over length on fp16 data (fp32 math)
// ---------------------------------------------------------------------------
__global__ __launch_bounds__(256) void softmax_len_h(__half* __restrict__ data)
{
    __shared__ float red[256];
    __half2* p = (__half2*)(data + (size_t)blockIdx.x * Ln);
    int t = threadIdx.x;
    float2 v[8];
    float m = -1e30f;
    #pragma unroll
    for (int i = 0; i < 8; i++) {
        v[i] = __half22float2(p[t + 256 * i]);
        m = fmaxf(m, fmaxf(v[i].x, v[i].y));
    }
    red[t] = m; __syncthreads();
    for (int off = 128; off > 0; off >>= 1) {
        if (t < off) red[t] = fmaxf(red[t], red[t + off]);
        __syncthreads();
    }
    m = red[0];
    __syncthreads();
    float s = 0.f;
    #pragma unroll
    for (int i = 0; i < 8; i++) {
        v[i].x = __expf(v[i].x - m);
        v[i].y = __expf(v[i].y - m);
        s += v[i].x + v[i].y;
    }
    red[t] = s; __syncthreads();
    for (int off = 128; off > 0; off >>= 1) {
        if (t < off) red[t] += red[t + off];
        __syncthreads();
    }
    float inv = 1.f / red[0];
    #pragma unroll
    for (int i = 0; i < 8; i++)
        p[t + 256 * i] = __floats2half2_rn(v[i].x * inv, v[i].y * inv);
}

// ---------------------------------------------------------------------------
// ctx partials (fp16 k, v inputs; fp32 accumulate)
// ---------------------------------------------------------------------------
__global__ __launch_bounds__(256) void ctx_kernel(
    const __half* __restrict__ kk, const __half* __restrict__ vv,
    float* __restrict__ ctxp)
{
    int bh = blockIdx.x;
    int sp = blockIdx.y;
    const __half* kb = kk + (size_t)bh * Dh * Ln;
    const __half* vb = vv + (size_t)bh * Dh * Ln;

    __shared__ float ks[64][33];
    __shared__ float vs[64][33];

    int tid = threadIdx.x;
    int lt = tid & 31, dr = tid >> 5;
    int tx = tid & 15, ty = tid >> 4;

    float acc[4][4];
    #pragma unroll
    for (int i = 0; i < 4; i++)
        #pragma unroll
        for (int j = 0; j < 4; j++) acc[i][j] = 0.f;

    int lbeg = sp * (Ln / NSPLIT);
    int lend = lbeg + (Ln / NSPLIT);
    for (int l0 = lbeg; l0 < lend; l0 += 32) {
        __syncthreads();
        #pragma unroll
        for (int r = 0; r < 8; r++) {
            int dk = dr + 8 * r;
            ks[dk][lt] = __half2float(kb[(size_t)dk * Ln + l0 + lt]);
            vs[dk][lt] = __half2float(vb[(size_t)dk * Ln + l0 + lt]);
        }
        __syncthreads();
        #pragma unroll
        for (int l2 = 0; l2 < 32; l2++) {
            float av[4], bw[4];
            #pragma unroll
            for (int i = 0; i < 4; i++) av[i] = ks[ty * 4 + i][l2];
            #pragma unroll
            for (int j = 0; j < 4; j++) bw[j] = vs[tx * 4 + j][l2];
            #pragma unroll
            for (int i = 0; i < 4; i++)
                #pragma unroll
                for (int j = 0; j < 4; j++)
                    acc[i][j] += av[i] * bw[j];
        }
    }
    #pragma unroll
    for (int i = 0; i < 4; i++)
        #pragma unroll
        for (int j = 0; j < 4; j++) {
            int dk = ty * 4 + i, dv = tx * 4 + j;
            ctxp[(((size_t)sp * 64 + bh) * 64 + dk) * 64 + dv] = acc[i][j];
        }
}

// ---------------------------------------------------------------------------
// att fused: head-softmax(q) inline + ctx^T apply + fp16 tiled output
// ---------------------------------------------------------------------------
__global__ __launch_bounds__(256) void att_fused(
    const float* __restrict__ ctxp, const float* __restrict__ q,
    __half* __restrict__ attc)
{
    int bh = blockIdx.y;
    int b = bh >> 3, h = bh & 7;
    __shared__ float cs[64][64];
    int tid = threadIdx.x;

    float4* cs4 = (float4*)cs;
    #pragma unroll
    for (int r = 0; r < 4; r++) {
        int idx = tid + 256 * r;
        float4 sum = make_float4(0.f, 0.f, 0.f, 0.f);
        #pragma unroll
        for (int s = 0; s < NSPLIT; s++) {
            const float4* p = (const float4*)(ctxp + ((size_t)s * 64 + bh) * 4096);
            float4 t = p[idx];
            sum.x += t.x; sum.y += t.y; sum.z += t.z; sum.w += t.w;
        }
        cs4[idx] = sum;
    }
    __syncthreads();

    int l = blockIdx.x * 256 + tid;
    const float* qb = q + (size_t)bh * Dh * Ln + l;

    float qv[64];
    float mx = -1e30f;
    #pragma unroll
    for (int d = 0; d < 64; d++) { qv[d] = qb[(size_t)d * Ln]; mx = fmaxf(mx, qv[d]); }
    float s = 0.f;
    #pragma unroll
    for (int d = 0; d < 64; d++) { qv[d] = __expf(qv[d] - mx); s += qv[d]; }
    float inv = 1.f / s;

    float acc[64];
    #pragma unroll
    for (int d = 0; d < 64; d++) acc[d] = 0.f;

    #pragma unroll 4
    for (int dk = 0; dk < 64; dk++) {
        float qq = qv[dk] * inv;
        #pragma unroll
        for (int j = 0; j < 16; j++) {
            float4 c4 = *(const float4*)&cs[dk][j * 4];
            acc[4 * j + 0] += c4.x * qq;
            acc[4 * j + 1] += c4.y * qq;
            acc[4 * j + 2] += c4.z * qq;
            acc[4 * j + 3] += c4.w * qq;
        }
    }

    char* db = (char*)(attc + (((size_t)b * 16 + blockIdx.x) * 8 + h) * 16384);
    #pragma unroll
    for (int j = 0; j < 8; j++) {
        uint4 w;
        w.x = pack2h(acc[8*j+0], acc[8*j+1]);
        w.y = pack2h(acc[8*j+2], acc[8*j+3]);
        w.z = pack2h(acc[8*j+4], acc[8*j+5]);
        w.w = pack2h(acc[8*j+6], acc[8*j+7]);
        *(uint4*)(db + swz128((uint32_t)tid * 128 + j * 16)) = w;
    }
}

// ---------------------------------------------------------------------------
// Channel LayerNorm over C=512 -> fp32 out (register-cached single pass)
// ---------------------------------------------------------------------------
__global__ __launch_bounds__(256) void ln_kernel(
    const float* __restrict__ in, float* __restrict__ out,
    const float* __restrict__ g, const float* __restrict__ be)
{
    __shared__ float ss[8][32], sq[8][32], smean[32], srstd[32];
    int blk = blockIdx.x;
    int b = blk >> 7;
    int li = threadIdx.x & 31;
    int l = ((blk & 127) << 5) + li;
    int r = threadIdx.x >> 5;
    const float* base = in + (size_t)b * Cc * Ln + l;

    float s = 0.f, s2 = 0.f;
    float x0[64];
    #pragma unroll
    for (int k2 = 0; k2 < 64; k2++) {
        int c = r * 64 + k2;
        float x = base[(size_t)c * Ln];
        x0[k2] = x;
        s += x; s2 += x * x;
    }
    ss[r][li] = s; sq[r][li] = s2;
    __syncthreads();
    if (r == 0) {
        float ts = ss[0][li], t2 = sq[0][li];
        #pragma unroll
        for (int rr = 1; rr < 8; rr++) { ts += ss[rr][li]; t2 += sq[rr][li]; }
        float mean = ts * (1.f / 512.f);
        float var = t2 * (1.f / 512.f) - mean * mean;
        smean[li] = mean;
        srstd[li] = rsqrtf(var + 1e-5f);
    }
    __syncthreads();
    float mean = smean[li], rstd = srstd[li];
    float* ob = out + (size_t)b * Cc * Ln + l;
    #pragma unroll
    for (int k2 = 0; k2 < 64; k2++) {
        int c = r * 64 + k2;
        ob[(size_t)c * Ln] = (x0[k2] - mean) * rstd * g[c] + be[c];
    }
}

// ---------------------------------------------------------------------------
// Channel LayerNorm -> fp16 tiled out
// ---------------------------------------------------------------------------
__global__ __launch_bounds__(256) void ln_h(
    const float* __restrict__ in, __half* __restrict__ outc,
    const float* __restrict__ g, const float* __restrict__ be)
{
    __shared__ float ss[8][32], sq[8][32], smean[32], srstd[32];
    int blk = blockIdx.x;
    int b = blk >> 7;
    int li = threadIdx.x & 31;
    int l = ((blk & 127) << 5) + li;
    int r = threadIdx.x >> 5;
    const float* base = in + (size_t)b * Cc * Ln + l;

    float s = 0.f, s2 = 0.f;
    float x0[64];
    #pragma unroll
    for (int k2 = 0; k2 < 64; k2++) {
        int c = r * 64 + k2;
        float x = base[(size_t)c * Ln];
        x0[k2] = x;
        s += x; s2 += x * x;
    }
    ss[r][li] = s; sq[r][li] = s2;
    __syncthreads();
    if (r == 0) {
        float ts = ss[0][li], t2 = sq[0][li];
        #pragma unroll
        for (int rr = 1; rr < 8; rr++) { ts += ss[rr][li]; t2 += sq[rr][li]; }
        float mean = ts * (1.f / 512.f);
        float var = t2 * (1.f / 512.f) - mean * mean;
        smean[li] = mean;
        srstd[li] = rsqrtf(var + 1e-5f);
    }
    __syncthreads();
    float mean = smean[li], rstd = srstd[li];

    char* db = (char*)(outc + (((size_t)b * 16 + (l >> 8)) * 8 + r) * 16384);
    uint32_t row = (uint32_t)(l & 255);
    #pragma unroll
    for (int j = 0; j < 8; j++) {
        float v[8];
        #pragma unroll
        for (int q2 = 0; q2 < 8; q2++) {
            int c = r * 64 + j * 8 + q2;
            v[q2] = (x0[j * 8 + q2] - mean) * rstd * g[c] + be[c];
        }
        uint4 w;
        w.x = pack2h(v[0], v[1]);
        w.y = pack2h(v[2], v[3]);
        w.z = pack2h(v[4], v[5]);
        w.w = pack2h(v[6], v[7]);
        *(uint4*)(db + swz128(row * 128 + j * 16)) = w;
    }
}

// ---------------------------------------------------------------------------
extern "C" void kernel_launch(void* const* d_in, const int* in_sizes, int n_in,
                              void* d_out, int out_size)
{
    const float* z1  = (const float*)d_in[0];
    const float* z2  = (const float*)d_in[1];
    const float* Wq  = (const float*)d_in[2];
    const float* bq  = (const float*)d_in[3];
    const float* Wk  = (const float*)d_in[4];
    const float* bkb = (const float*)d_in[5];
    const float* Wv  = (const float*)d_in[6];
    const float* bv  = (const float*)d_in[7];
    const float* Wr  = (const float*)d_in[8];
    const float* br  = (const float*)d_in[9];
    const float* g1  = (const float*)d_in[10];
    const float* be1 = (const float*)d_in[11];
    const float* W1  = (const float*)d_in[12];
    const float* b1  = (const float*)d_in[13];
    const float* W2  = (const float*)d_in[14];
    const float* b2  = (const float*)d_in[15];
    const float* g2  = (const float*)d_in[16];
    const float* be2 = (const float*)d_in[17];

    float* fs = nullptr;
    cudaGetSymbolAddress((void**)&fs, g_scratch);
    __half* hf = nullptr;
    cudaGetSymbolAddress((void**)&hf, g_hf);

    const size_t SZ = (size_t)Bn * Cc * Ln;   // 16777216
    float* q    = fs;
    __half* kh  = (__half*)(fs + SZ);
    __half* vh  = (__half*)(fs + 2 * SZ);
    float* z    = fs + 4 * SZ;
    float* y    = fs + 5 * SZ;
    float* ctxp = fs + 8 * SZ;

    cudaFuncSetAttribute(gemm_wm, cudaFuncAttributeMaxDynamicSharedMemorySize, GEMM_SMEM);
    cudaFuncSetAttribute(gemm_qkv, cudaFuncAttributeMaxDynamicSharedMemorySize, GEMM_SMEM);

    dim3 thr(256);
    conv_w_all<<<dim3(16, 8, 6), thr>>>(Wq, Wk, Wv, Wr, W1, W2, hf);
    conv_x2<<<dim3(8, 16, 16), thr>>>(z1, z2, hf + OFF_Z1C, hf + OFF_Z2C);

    // Merged Q/K/V projections (K,V -> fp16 flat)
    gemm_qkv<<<dim3(4, 32, 24), thr, GEMM_SMEM>>>(hf, bq, bkb, bv, q, kh, vh);

    // key softmax over length (fp16 in place)
    softmax_len_h<<<Bn * Cc, thr>>>(kh);

    // Attention core
    ctx_kernel<<<dim3(Bn * Hh, NSPLIT), thr>>>(kh, vh, ctxp);
    att_fused<<<dim3(Ln / 256, Bn * Hh), thr>>>(ctxp, q, hf + OFF_ATTC);

    // Reprojection + residual (fp32 out)
    gemm_wm<<<dim3(4, 32, 8), thr, GEMM_SMEM>>>(hf + OFF_WR, br, hf + OFF_ATTC, z, nullptr, z1, 512, 512, 0, 0);

    // LN1 -> fp16 tiled
    ln_h<<<Bn * (Ln / 32), thr>>>(z, hf + OFF_ZC, g1, be1);

    // FFN1 -> fp16 tiled h (ELU fused), FFN2 -> fp32 y
    gemm_wm<<<dim3(8, 32, 8), thr, GEMM_SMEM>>>(hf + OFF_W1, b1, hf + OFF_ZC, nullptr, hf + OFF_HC, nullptr, 1024, 512, 1, 1);
    gemm_wm<<<dim3(4, 32, 8), thr, GEMM_SMEM>>>(hf + OFF_W2, b2, hf + OFF_HC, y, nullptr, nullptr, 512, 1024, 0, 0);

    // LN2 -> output
    ln_kernel<<<Bn * (Ln / 32), thr>>>(y, (float*)d_out, g2, be2);
}

// round 10
// speedup vs baseline: 1.3675x; 1.0150x over previous
#include <cuda_runtime.h>
#include <cuda_fp16.h>
#include <cstdint>

// Problem constants
#define Bn  8
#define Cc  512
#define Ln  4096
#define Hh  8
#define Dh  64
#define NSPLIT 4

// ---------------------------------------------------------------------------
// Scratch
// ---------------------------------------------------------------------------
__device__ float g_scratch[135266304];
__device__ __half g_hf[102760448];

// half-element offsets into g_hf
#define OFF_Z1C  0ull
#define OFF_Z2C  16777216ull
#define OFF_ATTC 33554432ull
#define OFF_ZC   50331648ull
#define OFF_HC   67108864ull
#define OFF_WQ   100663296ull
#define OFF_WK   100925440ull
#define OFF_WV   101187584ull
#define OFF_WR   101449728ull
#define OFF_W1   101711872ull
#define OFF_W2   102236160ull

// ---------------------------------------------------------------------------
// Helpers
// ---------------------------------------------------------------------------
__device__ __forceinline__ uint32_t smem_u32(const void* p) {
    uint32_t a;
    asm("{ .reg .u64 t; cvta.to.shared.u64 t, %1; cvt.u32.u64 %0, t; }"
        : "=r"(a) : "l"(p));
    return a;
}
__device__ __host__ __forceinline__ uint32_t swz128(uint32_t off) {
    return off ^ ((off >> 3) & 0x70);
}
__device__ __forceinline__ void cpasync16(uint32_t d, const void* s) {
    asm volatile("cp.async.cg.shared.global [%0], [%1], 16;" :: "r"(d), "l"(s));
}
#define CP_COMMIT() asm volatile("cp.async.commit_group;" ::: "memory")
#define CP_WAIT(N)  asm volatile("cp.async.wait_group " #N ";" ::: "memory")

#define LDSM4(R, ADDR) \
    asm volatile("ldmatrix.sync.aligned.m8n8.x4.shared.b16 {%0,%1,%2,%3}, [%4];" \
        : "=r"((R)[0]), "=r"((R)[1]), "=r"((R)[2]), "=r"((R)[3]) : "r"(ADDR))

#define MMA16816(C, A, Bv) \
    asm volatile("mma.sync.aligned.m16n8k16.row.col.f32.f16.f16.f32 " \
        "{%0,%1,%2,%3}, {%4,%5,%6,%7}, {%8,%9}, {%0,%1,%2,%3};" \
        : "+f"((C)[0]), "+f"((C)[1]), "+f"((C)[2]), "+f"((C)[3]) \
        : "r"((A)[0]), "r"((A)[1]), "r"((A)[2]), "r"((A)[3]), \
          "r"((Bv)[0]), "r"((Bv)[1]))

__device__ __forceinline__ uint32_t pack2h(float a, float b) {
    __half2 h = __floats2half2_rn(a, b);
    return *(uint32_t*)&h;
}

#define STG 32768u
#define GEMM_SMEM 98304   // 3 stages

// ---------------------------------------------------------------------------
// Convert ALL weights in one launch. grid (16, 8, 6)
// ---------------------------------------------------------------------------
__global__ __launch_bounds__(256) void conv_w_all(
    const float* __restrict__ Wq, const float* __restrict__ Wk,
    const float* __restrict__ Wv, const float* __restrict__ Wr,
    const float* __restrict__ W1, const float* __restrict__ W2,
    __half* __restrict__ hf)
{
    int widx = blockIdx.z;
    const float* src;
    __half* dstb;
    int K, MT;
    switch (widx) {
        case 0: src = Wq; dstb = hf + OFF_WQ; K = 512;  MT = 4; break;
        case 1: src = Wk; dstb = hf + OFF_WK; K = 512;  MT = 4; break;
        case 2: src = Wv; dstb = hf + OFF_WV; K = 512;  MT = 4; break;
        case 3: src = Wr; dstb = hf + OFF_WR; K = 512;  MT = 4; break;
        case 4: src = W1; dstb = hf + OFF_W1; K = 512;  MT = 8; break;
        default: src = W2; dstb = hf + OFF_W2; K = 1024; MT = 4; break;
    }
    int NC = K >> 6;
    int kc = blockIdx.x, mt = blockIdx.y;
    if (kc >= NC || mt >= MT) return;
    char* db = (char*)(dstb + ((size_t)(mt * NC + kc)) * 8192);
    const float* sb = src + ((size_t)mt * 128) * K + kc * 64;
    for (int it = 0; it < 4; it++) {
        int u = threadIdx.x + 256 * it;
        int r = u >> 3, g = u & 7;
        float x0[8];
        #pragma unroll
        for (int q = 0; q < 2; q++) {
            float4 v = *(const float4*)(sb + (size_t)r * K + g * 8 + q * 4);
            x0[q*4+0]=v.x; x0[q*4+1]=v.y; x0[q*4+2]=v.z; x0[q*4+3]=v.w;
        }
        uint4 w;
        w.x = pack2h(x0[0], x0[1]);
        w.y = pack2h(x0[2], x0[3]);
        w.z = pack2h(x0[4], x0[5]);
        w.w = pack2h(x0[6], x0[7]);
        uint32_t sw = swz128((uint32_t)r * 128 + g * 16);
        *(uint4*)(db + sw) = w;
    }
}

// ---------------------------------------------------------------------------
// Convert+transpose z1 and z2 in one launch: grid (8, 16, 16)
// ---------------------------------------------------------------------------
__global__ __launch_bounds__(256) void conv_x2(
    const float* __restrict__ src1, const float* __restrict__ src2,
    __half* __restrict__ dst1, __half* __restrict__ dst2)
{
    const int K = 512;
    int kc = blockIdx.x, lt = blockIdx.y;
    int b = blockIdx.z & 7;
    const float* src = (blockIdx.z < 8) ? src1 : src2;
    __half* dstb = (blockIdx.z < 8) ? dst1 : dst2;
    int NC = K >> 6;
    __shared__ float sm[32][264];
    const float* sb = src + ((size_t)b * K + kc * 64) * Ln + (size_t)lt * 256;
    char* db = (char*)(dstb + (((size_t)b * 16 + lt) * NC + kc) * 16384);
    int t = threadIdx.x;
    for (int p = 0; p < 2; p++) {
        __syncthreads();
        #pragma unroll
        for (int i = 0; i < 8; i++) {
            int u = t + 256 * i;
            int kr = u >> 6;
            int lc = u & 63;
            float4 v = *(const float4*)(sb + ((size_t)(p * 32 + kr)) * Ln + lc * 4);
            sm[kr][lc*4+0]=v.x; sm[kr][lc*4+1]=v.y; sm[kr][lc*4+2]=v.z; sm[kr][lc*4+3]=v.w;
        }
        __syncthreads();
        #pragma unroll
        for (int g = 0; g < 4; g++) {
            float x0[8];
            #pragma unroll
            for (int j = 0; j < 8; j++) x0[j] = sm[g*8+j][t];
            uint4 w;
            w.x = pack2h(x0[0], x0[1]);
            w.y = pack2h(x0[2], x0[3]);
            w.z = pack2h(x0[4], x0[5]);
            w.w = pack2h(x0[6], x0[7]);
            uint32_t sw = swz128((uint32_t)t * 128 + (p * 32 + g * 8) * 2);
            *(uint4*)(db + sw) = w;
        }
    }
}

// ---------------------------------------------------------------------------
// Shared GEMM mainloop (256 threads, 8 warps 64x32, 128x128 tile, 3 stages)
// ---------------------------------------------------------------------------
#define GEMM_PROLOGUE() \
    uint32_t sbase = smem_u32(smem); \
    int tid = threadIdx.x, wid = tid >> 5, lane = tid & 31; \
    int wm = wid >> 2, wn = wid & 3; \
    int sub = lane >> 3, r = lane & 7; \
    uint32_t aRow[4], aMask[4]; \
    int kaddA = (sub >> 1) * 16; \
    _Pragma("unroll") \
    for (int i = 0; i < 4; i++) { \
        uint32_t row = wm * 64 + i * 16 + (sub & 1) * 8 + r; \
        aRow[i] = row * 128; \
        aMask[i] = (aRow[i] >> 3) & 0x70; \
    } \
    uint32_t bRow[2], bMask[2]; \
    int kaddB = (sub & 1) * 16; \
    _Pragma("unroll") \
    for (int j = 0; j < 2; j++) { \
        uint32_t row = wn * 32 + j * 16 + (sub >> 1) * 8 + r; \
        bRow[j] = row * 128; \
        bMask[j] = (bRow[j] >> 3) & 0x70; \
    } \
    float acc[4][4][4]; \
    _Pragma("unroll") \
    for (int i = 0; i < 4; i++) \
        _Pragma("unroll") \
        for (int j = 0; j < 4; j++) \
            _Pragma("unroll") \
            for (int q = 0; q < 4; q++) acc[i][j][q] = 0.f;

#define GEMM_LOAD_STAGE(kc, s) do { \
    uint32_t S = sbase + (uint32_t)(s) * STG; \
    const char* ah = Abase + (size_t)(kc) * 16384; \
    const char* bh = Bbase + (size_t)(kc) * 32768; \
    _Pragma("unroll") \
    for (int q = 0; q < 4; q++) { \
        uint32_t off = (uint32_t)tid * 64 + q * 16; \
        cpasync16(S + off,         ah + off); \
        cpasync16(S + 16384 + off, bh + off); \
    } \
} while (0)

#define GEMM_MAINLOOP(NC) \
    GEMM_LOAD_STAGE(0, 0); CP_COMMIT(); \
    if ((NC) > 1) { GEMM_LOAD_STAGE(1, 1); CP_COMMIT(); } \
    int sc = 0; \
    for (int c = 0; c < (NC); c++) { \
        CP_WAIT(1); \
        __syncthreads(); \
        if (c + 2 < (NC)) { \
            int s2 = sc + 2; if (s2 >= 3) s2 -= 3; \
            GEMM_LOAD_STAGE(c + 2, s2); CP_COMMIT(); \
        } \
        uint32_t S = sbase + (uint32_t)sc * STG; \
        _Pragma("unroll") \
        for (int kk = 0; kk < 4; kk++) { \
            int kb = kk * 32; \
            uint32_t aa[16], bb[8]; \
            _Pragma("unroll") \
            for (int i = 0; i < 4; i++) \
                LDSM4(&aa[i * 4], S + aRow[i] + (uint32_t)((kaddA + kb) ^ aMask[i])); \
            _Pragma("unroll") \
            for (int j = 0; j < 2; j++) \
                LDSM4(&bb[j * 4], S + 16384 + bRow[j] + (uint32_t)((kaddB + kb) ^ bMask[j])); \
            _Pragma("unroll") \
            for (int mi = 0; mi < 4; mi++) \
                _Pragma("unroll") \
                for (int nj = 0; nj < 4; nj++) \
                    MMA16816(acc[mi][nj], &aa[mi * 4], &bb[nj * 2]); \
        } \
        sc++; if (sc == 3) sc = 0; \
    }

// ---------------------------------------------------------------------------
// Merged Q/K/V projection GEMM: grid (4, 32, 24); z>>3 selects {Q,K,V}.
// All outputs fp16 flat [B, C, L].
// ---------------------------------------------------------------------------
__global__ __launch_bounds__(256, 2) void gemm_qkv(
    const __half* __restrict__ hf,
    const float* __restrict__ bq, const float* __restrict__ bk,
    const float* __restrict__ bv,
    __half* __restrict__ qh, __half* __restrict__ kh, __half* __restrict__ vh)
{
    extern __shared__ __align__(1024) char smem[];
    const int NC = 8;
    int mt = blockIdx.x, lt = blockIdx.y;
    int which = blockIdx.z >> 3, b = blockIdx.z & 7;

    const __half* Wc = (which == 0) ? hf + OFF_WQ : (which == 1) ? hf + OFF_WK : hf + OFF_WV;
    const float* bias = (which == 0) ? bq : (which == 1) ? bk : bv;
    const __half* Xc = (which == 0) ? hf + OFF_Z1C : hf + OFF_Z2C;
    __half* Out = (which == 0) ? qh : (which == 1) ? kh : vh;

    const char* Abase = (const char*)Wc + ((size_t)mt * NC) * 16384;
    int lt256 = lt >> 1, half = lt & 1;
    const char* Bbase = (const char*)Xc + (((size_t)b * 16 + lt256) * NC) * 32768
                        + (size_t)half * 16384;

    GEMM_PROLOGUE();
    GEMM_MAINLOOP(NC);

    int g = lane >> 2, tg = lane & 3;
    #pragma unroll
    for (int mi = 0; mi < 4; mi++) {
        #pragma unroll
        for (int h2 = 0; h2 < 2; h2++) {
            int m = mt * 128 + wm * 64 + mi * 16 + h2 * 8 + g;
            float bi = bias[m];
            size_t rowoff = ((size_t)b * 512 + m) * Ln + (size_t)lt * 128 + wn * 32;
            #pragma unroll
            for (int nj = 0; nj < 4; nj++) {
                int col = nj * 8 + 2 * tg;
                float v0 = acc[mi][nj][h2 * 2 + 0] + bi;
                float v1 = acc[mi][nj][h2 * 2 + 1] + bi;
                *(__half2*)(Out + rowoff + col) = __floats2half2_rn(v0, v1);
            }
        }
    }
}

// ---------------------------------------------------------------------------
// General GEMM. outmode 0: fp32 Out (+Res)(+ELU). outmode 1: fp16 tiled Outh.
// outmode 2: fp16 flat Outh (+Res fp32)(+ELU).
// ---------------------------------------------------------------------------
__global__ __launch_bounds__(256, 2) void gemm_wm(
    const __half* __restrict__ Wc, const float* __restrict__ bias,
    const __half* __restrict__ Xc, float* __restrict__ Out,
    __half* __restrict__ Outh,
    const float* __restrict__ Res, int M, int K, int act, int outmode)
{
    extern __shared__ __align__(1024) char smem[];
    const int NC = K >> 6;
    int mt = blockIdx.x, lt = blockIdx.y, b = blockIdx.z;

    const char* Abase = (const char*)Wc + ((size_t)mt * NC) * 16384;
    int lt256 = lt >> 1, half = lt & 1;
    const char* Bbase = (const char*)Xc + (((size_t)b * 16 + lt256) * NC) * 32768
                        + (size_t)half * 16384;

    GEMM_PROLOGUE();
    GEMM_MAINLOOP(NC);

    int g = lane >> 2, tg = lane & 3;

    if (outmode == 0) {
        #pragma unroll
        for (int mi = 0; mi < 4; mi++) {
            #pragma unroll
            for (int h2 = 0; h2 < 2; h2++) {
                int m = mt * 128 + wm * 64 + mi * 16 + h2 * 8 + g;
                float bi = bias[m];
                size_t rowoff = ((size_t)b * M + m) * Ln + (size_t)lt * 128 + wn * 32;
                #pragma unroll
                for (int nj = 0; nj < 4; nj++) {
                    int col = nj * 8 + 2 * tg;
                    float v0 = acc[mi][nj][h2 * 2 + 0] + bi;
                    float v1 = acc[mi][nj][h2 * 2 + 1] + bi;
                    if (Res) {
                        float2 r2 = *(const float2*)(Res + rowoff + col);
                        v0 += r2.x; v1 += r2.y;
                    }
                    if (act) {
                        v0 = v0 > 0.f ? v0 : expm1f(v0);
                        v1 = v1 > 0.f ? v1 : expm1f(v1);
                    }
                    *(float2*)(Out + rowoff + col) = make_float2(v0, v1);
                }
            }
        }
    } else if (outmode == 2) {
        #pragma unroll
        for (int mi = 0; mi < 4; mi++) {
            #pragma unroll
            for (int h2 = 0; h2 < 2; h2++) {
                int m = mt * 128 + wm * 64 + mi * 16 + h2 * 8 + g;
                float bi = bias[m];
                size_t rowoff = ((size_t)b * M + m) * Ln + (size_t)lt * 128 + wn * 32;
                #pragma unroll
                for (int nj = 0; nj < 4; nj++) {
                    int col = nj * 8 + 2 * tg;
                    float v0 = acc[mi][nj][h2 * 2 + 0] + bi;
                    float v1 = acc[mi][nj][h2 * 2 + 1] + bi;
                    if (Res) {
                        float2 r2 = *(const float2*)(Res + rowoff + col);
                        v0 += r2.x; v1 += r2.y;
                    }
                    if (act) {
                        v0 = v0 > 0.f ? v0 : expm1f(v0);
                        v1 = v1 > 0.f ? v1 : expm1f(v1);
                    }
                    *(__half2*)(Outh + rowoff + col) = __floats2half2_rn(v0, v1);
                }
            }
        }
    } else {
        __syncthreads();
        __half* smh = (__half*)smem;
        #pragma unroll
        for (int mi = 0; mi < 4; mi++) {
            #pragma unroll
            for (int h2 = 0; h2 < 2; h2++) {
                int ml = wm * 64 + mi * 16 + h2 * 8 + g;
                float bi = bias[mt * 128 + ml];
                #pragma unroll
                for (int nj = 0; nj < 4; nj++) {
                    int ll = wn * 32 + nj * 8 + 2 * tg;
                    float v0 = acc[mi][nj][h2 * 2 + 0] + bi;
                    float v1 = acc[mi][nj][h2 * 2 + 1] + bi;
                    if (act) {
                        v0 = v0 > 0.f ? v0 : expm1f(v0);
                        v1 = v1 > 0.f ? v1 : expm1f(v1);
                    }
                    smh[(uint32_t)ll * 136 + ml]       = __float2half(v0);
                    smh[(uint32_t)(ll + 1) * 136 + ml] = __float2half(v1);
                }
            }
        }
        __syncthreads();
        int rowbase = (lt & 1) * 128;
        int NCo = M >> 6;
        #pragma unroll
        for (int kc = 0; kc < 2; kc++) {
            char* db = (char*)(Outh + (((size_t)b * 16 + lt256) * NCo + (mt * 2 + kc)) * 16384);
            #pragma unroll
            for (int it = 0; it < 4; it++) {
                int u = tid + 256 * it;
                int row = u >> 3, j = u & 7;
                uint4 w = *(uint4*)&smh[(uint32_t)row * 136 + kc * 64 + j * 8];
                *(uint4*)(db + swz128((uint32_t)(rowbase + row) * 128 + j * 16)) = w;
            }
        }
    }
}

// ---------------------------------------------------------------------------
// ctx partials with inline exp (no pre-softmax): reads RAW k (fp16), v (fp16).
// ctxp[sp][bh][dk][dv] = sum_l exp(k[dk,l]) v[dv,l]   (l in split sp)
// zp[sp][bh][dk]       = sum_l exp(k[dk,l])
// k values are O(0.5) so exp without max-subtraction is fp32-safe.
// ---------------------------------------------------------------------------
__global__ __launch_bounds__(256) void ctx_kernel(
    const __half* __restrict__ kk, const __half* __restrict__ vv,
    float* __restrict__ ctxp, float* __restrict__ zp)
{
    int bh = blockIdx.x;
    int sp = blockIdx.y;
    const __half* kb = kk + (size_t)bh * Dh * Ln;
    const __half* vb = vv + (size_t)bh * Dh * Ln;

    __shared__ float ks[64][33];
    __shared__ float vs[64][33];

    int tid = threadIdx.x;
    int lt = tid & 31, dr = tid >> 5;
    int tx = tid & 15, ty = tid >> 4;

    float acc[4][4];
    float zacc[4];
    #pragma unroll
    for (int i = 0; i < 4; i++) {
        zacc[i] = 0.f;
        #pragma unroll
        for (int j = 0; j < 4; j++) acc[i][j] = 0.f;
    }

    int lbeg = sp * (Ln / NSPLIT);
    int lend = lbeg + (Ln / NSPLIT);
    for (int l0 = lbeg; l0 < lend; l0 += 32) {
        __syncthreads();
        #pragma unroll
        for (int r = 0; r < 8; r++) {
            int dk = dr + 8 * r;
            ks[dk][lt] = __expf(__half2float(kb[(size_t)dk * Ln + l0 + lt]));
            vs[dk][lt] = __half2float(vb[(size_t)dk * Ln + l0 + lt]);
        }
        __syncthreads();
        #pragma unroll
        for (int l2 = 0; l2 < 32; l2++) {
            float av[4], bw[4];
            #pragma unroll
            for (int i = 0; i < 4; i++) av[i] = ks[ty * 4 + i][l2];
            #pragma unroll
            for (int j = 0; j < 4; j++) bw[j] = vs[tx * 4 + j][l2];
            #pragma unroll
            for (int i = 0; i < 4; i++) {
                zacc[i] += av[i];
                #pragma unroll
                for (int j = 0; j < 4; j++)
                    acc[i][j] += av[i] * bw[j];
            }
        }
    }
    #pragma unroll
    for (int i = 0; i < 4; i++)
        #pragma unroll
        for (int j = 0; j < 4; j++) {
            int dk = ty * 4 + i, dv = tx * 4 + j;
            ctxp[(((size_t)sp * 64 + bh) * 64 + dk) * 64 + dv] = acc[i][j];
        }
    if (tx == 0) {
        #pragma unroll
        for (int i = 0; i < 4; i++)
            zp[((size_t)sp * 64 + bh) * 64 + ty * 4 + i] = zacc[i];
    }
}

// ---------------------------------------------------------------------------
// att fused: normalize ctx by Z, head-softmax(q fp16) inline, fp16 tiled out
// ---------------------------------------------------------------------------
__global__ __launch_bounds__(256) void att_fused(
    const float* __restrict__ ctxp, const float* __restrict__ zp,
    const __half* __restrict__ qh, __half* __restrict__ attc)
{
    int bh = blockIdx.y;
    int b = bh >> 3, h = bh & 7;
    __shared__ float cs[64][64];
    __shared__ float zinv[64];
    int tid = threadIdx.x;

    if (tid < 64) {
        float zs = 0.f;
        #pragma unroll
        for (int s = 0; s < NSPLIT; s++)
            zs += zp[((size_t)s * 64 + bh) * 64 + tid];
        zinv[tid] = 1.f / zs;
    }
    __syncthreads();

    float4* cs4 = (float4*)cs;
    #pragma unroll
    for (int r = 0; r < 4; r++) {
        int idx = tid + 256 * r;
        float zi = zinv[idx >> 4];
        float4 sum = make_float4(0.f, 0.f, 0.f, 0.f);
        #pragma unroll
        for (int s = 0; s < NSPLIT; s++) {
            const float4* p = (const float4*)(ctxp + ((size_t)s * 64 + bh) * 4096);
            float4 t = p[idx];
            sum.x += t.x; sum.y += t.y; sum.z += t.z; sum.w += t.w;
        }
        sum.x *= zi; sum.y *= zi; sum.z *= zi; sum.w *= zi;
        cs4[idx] = sum;
    }
    __syncthreads();

    int l = blockIdx.x * 256 + tid;
    const __half* qb = qh + (size_t)bh * Dh * Ln + l;

    float qv[64];
    float mx = -1e30f;
    #pragma unroll
    for (int d = 0; d < 64; d++) {
        qv[d] = __half2float(qb[(size_t)d * Ln]);
        mx = fmaxf(mx, qv[d]);
    }
    float s = 0.f;
    #pragma unroll
    for (int d = 0; d < 64; d++) { qv[d] = __expf(qv[d] - mx); s += qv[d]; }
    float inv = 1.f / s;

    float acc[64];
    #pragma unroll
    for (int d = 0; d < 64; d++) acc[d] = 0.f;

    #pragma unroll 4
    for (int dk = 0; dk < 64; dk++) {
        float qq = qv[dk] * inv;
        #pragma unroll
        for (int j = 0; j < 16; j++) {
            float4 c4 = *(const float4*)&cs[dk][j * 4];
            acc[4 * j + 0] += c4.x * qq;
            acc[4 * j + 1] += c4.y * qq;
            acc[4 * j + 2] += c4.z * qq;
            acc[4 * j + 3] += c4.w * qq;
        }
    }

    char* db = (char*)(attc + (((size_t)b * 16 + blockIdx.x) * 8 + h) * 16384);
    #pragma unroll
    for (int j = 0; j < 8; j++) {
        uint4 w;
        w.x = pack2h(acc[8*j+0], acc[8*j+1]);
        w.y = pack2h(acc[8*j+2], acc[8*j+3]);
        w.z = pack2h(acc[8*j+4], acc[8*j+5]);
        w.w = pack2h(acc[8*j+6], acc[8*j+7]);
        *(uint4*)(db + swz128((uint32_t)tid * 128 + j * 16)) = w;
    }
}

// ---------------------------------------------------------------------------
// Channel LayerNorm over C=512, fp16 in -> fp32 out (single pass, reg cache)
// ---------------------------------------------------------------------------
__global__ __launch_bounds__(256) void ln_kernel(
    const __half* __restrict__ in, float* __restrict__ out,
    const float* __restrict__ g, const float* __restrict__ be)
{
    __shared__ float ss[8][32], sq[8][32], smean[32], srstd[32];
    int blk = blockIdx.x;
    int b = blk >> 7;
    int li = threadIdx.x & 31;
    int l = ((blk & 127) << 5) + li;
    int r = threadIdx.x >> 5;
    const __half* base = in + (size_t)b * Cc * Ln + l;

    float s = 0.f, s2 = 0.f;
    float x0[64];
    #pragma unroll
    for (int k2 = 0; k2 < 64; k2++) {
        int c = r * 64 + k2;
        float x = __half2float(base[(size_t)c * Ln]);
        x0[k2] = x;
        s += x; s2 += x * x;
    }
    ss[r][li] = s; sq[r][li] = s2;
    __syncthreads();
    if (r == 0) {
        float ts = ss[0][li], t2 = sq[0][li];
        #pragma unroll
        for (int rr = 1; rr < 8; rr++) { ts += ss[rr][li]; t2 += sq[rr][li]; }
        float mean = ts * (1.f / 512.f);
        float var = t2 * (1.f / 512.f) - mean * mean;
        smean[li] = mean;
        srstd[li] = rsqrtf(var + 1e-5f);
    }
    __syncthreads();
    float mean = smean[li], rstd = srstd[li];
    float* ob = out + (size_t)b * Cc * Ln + l;
    #pragma unroll
    for (int k2 = 0; k2 < 64; k2++) {
        int c = r * 64 + k2;
        ob[(size_t)c * Ln] = (x0[k2] - mean) * rstd * g[c] + be[c];
    }
}

// ---------------------------------------------------------------------------
// Channel LayerNorm, fp16 in -> fp16 tiled out
// ---------------------------------------------------------------------------
__global__ __launch_bounds__(256) void ln_h(
    const __half* __restrict__ in, __half* __restrict__ outc,
    const float* __restrict__ g, const float* __restrict__ be)
{
    __shared__ float ss[8][32], sq[8][32], smean[32], srstd[32];
    int blk = blockIdx.x;
    int b = blk >> 7;
    int li = threadIdx.x & 31;
    int l = ((blk & 127) << 5) + li;
    int r = threadIdx.x >> 5;
    const __half* base = in + (size_t)b * Cc * Ln + l;

    float s = 0.f, s2 = 0.f;
    float x0[64];
    #pragma unroll
    for (int k2 = 0; k2 < 64; k2++) {
        int c = r * 64 + k2;
        float x = __half2float(base[(size_t)c * Ln]);
        x0[k2] = x;
        s += x; s2 += x * x;
    }
    ss[r][li] = s; sq[r][li] = s2;
    __syncthreads();
    if (r == 0) {
        float ts = ss[0][li], t2 = sq[0][li];
        #pragma unroll
        for (int rr = 1; rr < 8; rr++) { ts += ss[rr][li]; t2 += sq[rr][li]; }
        float mean = ts * (1.f / 512.f);
        float var = t2 * (1.f / 512.f) - mean * mean;
        smean[li] = mean;
        srstd[li] = rsqrtf(var + 1e-5f);
    }
    __syncthreads();
    float mean = smean[li], rstd = srstd[li];

    char* db = (char*)(outc + (((size_t)b * 16 + (l >> 8)) * 8 + r) * 16384);
    uint32_t row = (uint32_t)(l & 255);
    #pragma unroll
    for (int j = 0; j < 8; j++) {
        float v[8];
        #pragma unroll
        for (int q2 = 0; q2 < 8; q2++) {
            int c = r * 64 + j * 8 + q2;
            v[q2] = (x0[j * 8 + q2] - mean) * rstd * g[c] + be[c];
        }
        uint4 w;
        w.x = pack2h(v[0], v[1]);
        w.y = pack2h(v[2], v[3]);
        w.z = pack2h(v[4], v[5]);
        w.w = pack2h(v[6], v[7]);
        *(uint4*)(db + swz128(row * 128 + j * 16)) = w;
    }
}

// ---------------------------------------------------------------------------
extern "C" void kernel_launch(void* const* d_in, const int* in_sizes, int n_in,
                              void* d_out, int out_size)
{
    const float* z1  = (const float*)d_in[0];
    const float* z2  = (const float*)d_in[1];
    const float* Wq  = (const float*)d_in[2];
    const float* bq  = (const float*)d_in[3];
    const float* Wk  = (const float*)d_in[4];
    const float* bkb = (const float*)d_in[5];
    const float* Wv  = (const float*)d_in[6];
    const float* bv  = (const float*)d_in[7];
    const float* Wr  = (const float*)d_in[8];
    const float* br  = (const float*)d_in[9];
    const float* g1  = (const float*)d_in[10];
    const float* be1 = (const float*)d_in[11];
    const float* W1  = (const float*)d_in[12];
    const float* b1  = (const float*)d_in[13];
    const float* W2  = (const float*)d_in[14];
    const float* b2  = (const float*)d_in[15];
    const float* g2  = (const float*)d_in[16];
    const float* be2 = (const float*)d_in[17];

    float* fs = nullptr;
    cudaGetSymbolAddress((void**)&fs, g_scratch);
    __half* hf = nullptr;
    cudaGetSymbolAddress((void**)&hf, g_hf);

    const size_t SZ = (size_t)Bn * Cc * Ln;   // 16777216
    __half* qh  = (__half*)(fs);
    __half* kh  = (__half*)(fs + SZ);
    __half* vh  = (__half*)(fs + 2 * SZ);
    float*  zp  = fs + 3 * SZ;                // NSPLIT*64*64 floats
    __half* zh  = (__half*)(fs + 4 * SZ);
    __half* yh  = (__half*)(fs + 5 * SZ);
    float* ctxp = fs + 8 * SZ;

    cudaFuncSetAttribute(gemm_wm, cudaFuncAttributeMaxDynamicSharedMemorySize, GEMM_SMEM);
    cudaFuncSetAttribute(gemm_qkv, cudaFuncAttributeMaxDynamicSharedMemorySize, GEMM_SMEM);

    dim3 thr(256);
    conv_w_all<<<dim3(16, 8, 6), thr>>>(Wq, Wk, Wv, Wr, W1, W2, hf);
    conv_x2<<<dim3(8, 16, 16), thr>>>(z1, z2, hf + OFF_Z1C, hf + OFF_Z2C);

    // Merged Q/K/V projections (all fp16 flat)
    gemm_qkv<<<dim3(4, 32, 24), thr, GEMM_SMEM>>>(hf, bq, bkb, bv, qh, kh, vh);

    // Attention core (softmax over length folded into ctx via exp + Z)
    ctx_kernel<<<dim3(Bn * Hh, NSPLIT), thr>>>(kh, vh, ctxp, zp);
    att_fused<<<dim3(Ln / 256, Bn * Hh), thr>>>(ctxp, zp, qh, hf + OFF_ATTC);

    // Reprojection + residual -> fp16 flat z
    gemm_wm<<<dim3(4, 32, 8), thr, GEMM_SMEM>>>(hf + OFF_WR, br, hf + OFF_ATTC, nullptr, zh, z1, 512, 512, 0, 2);

    // LN1 (fp16 in) -> fp16 tiled
    ln_h<<<Bn * (Ln / 32), thr>>>(zh, hf + OFF_ZC, g1, be1);

    // FFN1 -> fp16 tiled h (ELU fused), FFN2 -> fp16 flat y
    gemm_wm<<<dim3(8, 32, 8), thr, GEMM_SMEM>>>(hf + OFF_W1, b1, hf + OFF_ZC, nullptr, hf + OFF_HC, nullptr, 1024, 512, 1, 1);
    gemm_wm<<<dim3(4, 32, 8), thr, GEMM_SMEM>>>(hf + OFF_W2, b2, hf + OFF_HC, nullptr, yh, nullptr, 512, 1024, 0, 2);

    // LN2 (fp16 in) -> fp32 output
    ln_kernel<<<Bn * (Ln / 32), thr>>>(yh, (float*)d_out, g2, be2);
}

// round 11
// speedup vs baseline: 1.4701x; 1.0750x over previous
#include <cuda_runtime.h>
#include <cuda_fp16.h>
#include <cstdint>

// Problem constants
#define Bn  8
#define Cc  512
#define Ln  4096
#define Hh  8
#define Dh  64
#define NSPLIT 8

// ---------------------------------------------------------------------------
// Scratch
// ---------------------------------------------------------------------------
__device__ float g_scratch[135266304];
__device__ __half g_hf[102760448];

// half-element offsets into g_hf
#define OFF_Z1C  0ull
#define OFF_Z2C  16777216ull
#define OFF_ATTC 33554432ull
#define OFF_ZC   50331648ull
#define OFF_HC   67108864ull
#define OFF_WQ   100663296ull
#define OFF_WK   100925440ull
#define OFF_WV   101187584ull
#define OFF_WR   101449728ull
#define OFF_W1   101711872ull
#define OFF_W2   102236160ull

// ---------------------------------------------------------------------------
// Helpers
// ---------------------------------------------------------------------------
__device__ __forceinline__ uint32_t smem_u32(const void* p) {
    uint32_t a;
    asm("{ .reg .u64 t; cvta.to.shared.u64 t, %1; cvt.u32.u64 %0, t; }"
        : "=r"(a) : "l"(p));
    return a;
}
__device__ __host__ __forceinline__ uint32_t swz128(uint32_t off) {
    return off ^ ((off >> 3) & 0x70);
}
__device__ __forceinline__ void cpasync16(uint32_t d, const void* s) {
    asm volatile("cp.async.cg.shared.global [%0], [%1], 16;" :: "r"(d), "l"(s));
}
#define CP_COMMIT() asm volatile("cp.async.commit_group;" ::: "memory")
#define CP_WAIT(N)  asm volatile("cp.async.wait_group " #N ";" ::: "memory")

#define LDSM4(R, ADDR) \
    asm volatile("ldmatrix.sync.aligned.m8n8.x4.shared.b16 {%0,%1,%2,%3}, [%4];" \
        : "=r"((R)[0]), "=r"((R)[1]), "=r"((R)[2]), "=r"((R)[3]) : "r"(ADDR))

#define MMA16816(C, A, Bv) \
    asm volatile("mma.sync.aligned.m16n8k16.row.col.f32.f16.f16.f32 " \
        "{%0,%1,%2,%3}, {%4,%5,%6,%7}, {%8,%9}, {%0,%1,%2,%3};" \
        : "+f"((C)[0]), "+f"((C)[1]), "+f"((C)[2]), "+f"((C)[3]) \
        : "r"((A)[0]), "r"((A)[1]), "r"((A)[2]), "r"((A)[3]), \
          "r"((Bv)[0]), "r"((Bv)[1]))

__device__ __forceinline__ uint32_t pack2h(float a, float b) {
    __half2 h = __floats2half2_rn(a, b);
    return *(uint32_t*)&h;
}

#define STG 32768u
#define GEMM_SMEM 98304   // 3 stages

// ---------------------------------------------------------------------------
// Convert ALL weights in one launch. grid (16, 8, 6)
// ---------------------------------------------------------------------------
__global__ __launch_bounds__(256) void conv_w_all(
    const float* __restrict__ Wq, const float* __restrict__ Wk,
    const float* __restrict__ Wv, const float* __restrict__ Wr,
    const float* __restrict__ W1, const float* __restrict__ W2,
    __half* __restrict__ hf)
{
    int widx = blockIdx.z;
    const float* src;
    __half* dstb;
    int K, MT;
    switch (widx) {
        case 0: src = Wq; dstb = hf + OFF_WQ; K = 512;  MT = 4; break;
        case 1: src = Wk; dstb = hf + OFF_WK; K = 512;  MT = 4; break;
        case 2: src = Wv; dstb = hf + OFF_WV; K = 512;  MT = 4; break;
        case 3: src = Wr; dstb = hf + OFF_WR; K = 512;  MT = 4; break;
        case 4: src = W1; dstb = hf + OFF_W1; K = 512;  MT = 8; break;
        default: src = W2; dstb = hf + OFF_W2; K = 1024; MT = 4; break;
    }
    int NC = K >> 6;
    int kc = blockIdx.x, mt = blockIdx.y;
    if (kc >= NC || mt >= MT) return;
    char* db = (char*)(dstb + ((size_t)(mt * NC + kc)) * 8192);
    const float* sb = src + ((size_t)mt * 128) * K + kc * 64;
    for (int it = 0; it < 4; it++) {
        int u = threadIdx.x + 256 * it;
        int r = u >> 3, g = u & 7;
        float x0[8];
        #pragma unroll
        for (int q = 0; q < 2; q++) {
            float4 v = *(const float4*)(sb + (size_t)r * K + g * 8 + q * 4);
            x0[q*4+0]=v.x; x0[q*4+1]=v.y; x0[q*4+2]=v.z; x0[q*4+3]=v.w;
        }
        uint4 w;
        w.x = pack2h(x0[0], x0[1]);
        w.y = pack2h(x0[2], x0[3]);
        w.z = pack2h(x0[4], x0[5]);
        w.w = pack2h(x0[6], x0[7]);
        uint32_t sw = swz128((uint32_t)r * 128 + g * 16);
        *(uint4*)(db + sw) = w;
    }
}

// ---------------------------------------------------------------------------
// Convert+transpose z1 and z2 in one launch: grid (8, 16, 16)
// ---------------------------------------------------------------------------
__global__ __launch_bounds__(256) void conv_x2(
    const float* __restrict__ src1, const float* __restrict__ src2,
    __half* __restrict__ dst1, __half* __restrict__ dst2)
{
    const int K = 512;
    int kc = blockIdx.x, lt = blockIdx.y;
    int b = blockIdx.z & 7;
    const float* src = (blockIdx.z < 8) ? src1 : src2;
    __half* dstb = (blockIdx.z < 8) ? dst1 : dst2;
    int NC = K >> 6;
    __shared__ float sm[32][264];
    const float* sb = src + ((size_t)b * K + kc * 64) * Ln + (size_t)lt * 256;
    char* db = (char*)(dstb + (((size_t)b * 16 + lt) * NC + kc) * 16384);
    int t = threadIdx.x;
    for (int p = 0; p < 2; p++) {
        __syncthreads();
        #pragma unroll
        for (int i = 0; i < 8; i++) {
            int u = t + 256 * i;
            int kr = u >> 6;
            int lc = u & 63;
            float4 v = *(const float4*)(sb + ((size_t)(p * 32 + kr)) * Ln + lc * 4);
            sm[kr][lc*4+0]=v.x; sm[kr][lc*4+1]=v.y; sm[kr][lc*4+2]=v.z; sm[kr][lc*4+3]=v.w;
        }
        __syncthreads();
        #pragma unroll
        for (int g = 0; g < 4; g++) {
            float x0[8];
            #pragma unroll
            for (int j = 0; j < 8; j++) x0[j] = sm[g*8+j][t];
            uint4 w;
            w.x = pack2h(x0[0], x0[1]);
            w.y = pack2h(x0[2], x0[3]);
            w.z = pack2h(x0[4], x0[5]);
            w.w = pack2h(x0[6], x0[7]);
            uint32_t sw = swz128((uint32_t)t * 128 + (p * 32 + g * 8) * 2);
            *(uint4*)(db + sw) = w;
        }
    }
}

// ---------------------------------------------------------------------------
// Shared GEMM mainloop (256 threads, 8 warps 64x32, 128x128 tile, 3 stages)
// ---------------------------------------------------------------------------
#define GEMM_PROLOGUE() \
    uint32_t sbase = smem_u32(smem); \
    int tid = threadIdx.x, wid = tid >> 5, lane = tid & 31; \
    int wm = wid >> 2, wn = wid & 3; \
    int sub = lane >> 3, r = lane & 7; \
    uint32_t aRow[4], aMask[4]; \
    int kaddA = (sub >> 1) * 16; \
    _Pragma("unroll") \
    for (int i = 0; i < 4; i++) { \
        uint32_t row = wm * 64 + i * 16 + (sub & 1) * 8 + r; \
        aRow[i] = row * 128; \
        aMask[i] = (aRow[i] >> 3) & 0x70; \
    } \
    uint32_t bRow[2], bMask[2]; \
    int kaddB = (sub & 1) * 16; \
    _Pragma("unroll") \
    for (int j = 0; j < 2; j++) { \
        uint32_t row = wn * 32 + j * 16 + (sub >> 1) * 8 + r; \
        bRow[j] = row * 128; \
        bMask[j] = (bRow[j] >> 3) & 0x70; \
    } \
    float acc[4][4][4]; \
    _Pragma("unroll") \
    for (int i = 0; i < 4; i++) \
        _Pragma("unroll") \
        for (int j = 0; j < 4; j++) \
            _Pragma("unroll") \
            for (int q = 0; q < 4; q++) acc[i][j][q] = 0.f;

#define GEMM_LOAD_STAGE(kc, s) do { \
    uint32_t S = sbase + (uint32_t)(s) * STG; \
    const char* ah = Abase + (size_t)(kc) * 16384; \
    const char* bh = Bbase + (size_t)(kc) * 32768; \
    _Pragma("unroll") \
    for (int q = 0; q < 4; q++) { \
        uint32_t off = (uint32_t)tid * 64 + q * 16; \
        cpasync16(S + off,         ah + off); \
        cpasync16(S + 16384 + off, bh + off); \
    } \
} while (0)

#define GEMM_MAINLOOP(NC) \
    GEMM_LOAD_STAGE(0, 0); CP_COMMIT(); \
    if ((NC) > 1) { GEMM_LOAD_STAGE(1, 1); CP_COMMIT(); } \
    int sc = 0; \
    for (int c = 0; c < (NC); c++) { \
        CP_WAIT(1); \
        __syncthreads(); \
        if (c + 2 < (NC)) { \
            int s2 = sc + 2; if (s2 >= 3) s2 -= 3; \
            GEMM_LOAD_STAGE(c + 2, s2); CP_COMMIT(); \
        } \
        uint32_t S = sbase + (uint32_t)sc * STG; \
        _Pragma("unroll") \
        for (int kk = 0; kk < 4; kk++) { \
            int kb = kk * 32; \
            uint32_t aa[16], bb[8]; \
            _Pragma("unroll") \
            for (int i = 0; i < 4; i++) \
                LDSM4(&aa[i * 4], S + aRow[i] + (uint32_t)((kaddA + kb) ^ aMask[i])); \
            _Pragma("unroll") \
            for (int j = 0; j < 2; j++) \
                LDSM4(&bb[j * 4], S + 16384 + bRow[j] + (uint32_t)((kaddB + kb) ^ bMask[j])); \
            _Pragma("unroll") \
            for (int mi = 0; mi < 4; mi++) \
                _Pragma("unroll") \
                for (int nj = 0; nj < 4; nj++) \
                    MMA16816(acc[mi][nj], &aa[mi * 4], &bb[nj * 2]); \
        } \
        sc++; if (sc == 3) sc = 0; \
    }

// ---------------------------------------------------------------------------
// Merged Q/K/V projection GEMM: grid (4, 32, 24); z>>3 selects {Q,K,V}.
// All outputs fp16 flat [B, C, L].
// ---------------------------------------------------------------------------
__global__ __launch_bounds__(256, 2) void gemm_qkv(
    const __half* __restrict__ hf,
    const float* __restrict__ bq, const float* __restrict__ bk,
    const float* __restrict__ bv,
    __half* __restrict__ qh, __half* __restrict__ kh, __half* __restrict__ vh)
{
    extern __shared__ __align__(1024) char smem[];
    const int NC = 8;
    int mt = blockIdx.x, lt = blockIdx.y;
    int which = blockIdx.z >> 3, b = blockIdx.z & 7;

    const __half* Wc = (which == 0) ? hf + OFF_WQ : (which == 1) ? hf + OFF_WK : hf + OFF_WV;
    const float* bias = (which == 0) ? bq : (which == 1) ? bk : bv;
    const __half* Xc = (which == 0) ? hf + OFF_Z1C : hf + OFF_Z2C;
    __half* Out = (which == 0) ? qh : (which == 1) ? kh : vh;

    const char* Abase = (const char*)Wc + ((size_t)mt * NC) * 16384;
    int lt256 = lt >> 1, half = lt & 1;
    const char* Bbase = (const char*)Xc + (((size_t)b * 16 + lt256) * NC) * 32768
                        + (size_t)half * 16384;

    GEMM_PROLOGUE();
    GEMM_MAINLOOP(NC);

    int g = lane >> 2, tg = lane & 3;
    #pragma unroll
    for (int mi = 0; mi < 4; mi++) {
        #pragma unroll
        for (int h2 = 0; h2 < 2; h2++) {
            int m = mt * 128 + wm * 64 + mi * 16 + h2 * 8 + g;
            float bi = bias[m];
            size_t rowoff = ((size_t)b * 512 + m) * Ln + (size_t)lt * 128 + wn * 32;
            #pragma unroll
            for (int nj = 0; nj < 4; nj++) {
                int col = nj * 8 + 2 * tg;
                float v0 = acc[mi][nj][h2 * 2 + 0] + bi;
                float v1 = acc[mi][nj][h2 * 2 + 1] + bi;
                *(__half2*)(Out + rowoff + col) = __floats2half2_rn(v0, v1);
            }
        }
    }
}

// ---------------------------------------------------------------------------
// General GEMM. outmode 0: fp32 Out (+Res)(+ELU). outmode 1: fp16 tiled Outh.
// outmode 2: fp16 flat Outh (+Res fp32)(+ELU).
// ---------------------------------------------------------------------------
__global__ __launch_bounds__(256, 2) void gemm_wm(
    const __half* __restrict__ Wc, const float* __restrict__ bias,
    const __half* __restrict__ Xc, float* __restrict__ Out,
    __half* __restrict__ Outh,
    const float* __restrict__ Res, int M, int K, int act, int outmode)
{
    extern __shared__ __align__(1024) char smem[];
    const int NC = K >> 6;
    int mt = blockIdx.x, lt = blockIdx.y, b = blockIdx.z;

    const char* Abase = (const char*)Wc + ((size_t)mt * NC) * 16384;
    int lt256 = lt >> 1, half = lt & 1;
    const char* Bbase = (const char*)Xc + (((size_t)b * 16 + lt256) * NC) * 32768
                        + (size_t)half * 16384;

    GEMM_PROLOGUE();
    GEMM_MAINLOOP(NC);

    int g = lane >> 2, tg = lane & 3;

    if (outmode == 0) {
        #pragma unroll
        for (int mi = 0; mi < 4; mi++) {
            #pragma unroll
            for (int h2 = 0; h2 < 2; h2++) {
                int m = mt * 128 + wm * 64 + mi * 16 + h2 * 8 + g;
                float bi = bias[m];
                size_t rowoff = ((size_t)b * M + m) * Ln + (size_t)lt * 128 + wn * 32;
                #pragma unroll
                for (int nj = 0; nj < 4; nj++) {
                    int col = nj * 8 + 2 * tg;
                    float v0 = acc[mi][nj][h2 * 2 + 0] + bi;
                    float v1 = acc[mi][nj][h2 * 2 + 1] + bi;
                    if (Res) {
                        float2 r2 = *(const float2*)(Res + rowoff + col);
                        v0 += r2.x; v1 += r2.y;
                    }
                    if (act) {
                        v0 = v0 > 0.f ? v0 : expm1f(v0);
                        v1 = v1 > 0.f ? v1 : expm1f(v1);
                    }
                    *(float2*)(Out + rowoff + col) = make_float2(v0, v1);
                }
            }
        }
    } else if (outmode == 2) {
        #pragma unroll
        for (int mi = 0; mi < 4; mi++) {
            #pragma unroll
            for (int h2 = 0; h2 < 2; h2++) {
                int m = mt * 128 + wm * 64 + mi * 16 + h2 * 8 + g;
                float bi = bias[m];
                size_t rowoff = ((size_t)b * M + m) * Ln + (size_t)lt * 128 + wn * 32;
                #pragma unroll
                for (int nj = 0; nj < 4; nj++) {
                    int col = nj * 8 + 2 * tg;
                    float v0 = acc[mi][nj][h2 * 2 + 0] + bi;
                    float v1 = acc[mi][nj][h2 * 2 + 1] + bi;
                    if (Res) {
                        float2 r2 = *(const float2*)(Res + rowoff + col);
                        v0 += r2.x; v1 += r2.y;
                    }
                    if (act) {
                        v0 = v0 > 0.f ? v0 : expm1f(v0);
                        v1 = v1 > 0.f ? v1 : expm1f(v1);
                    }
                    *(__half2*)(Outh + rowoff + col) = __floats2half2_rn(v0, v1);
                }
            }
        }
    } else {
        __syncthreads();
        __half* smh = (__half*)smem;
        #pragma unroll
        for (int mi = 0; mi < 4; mi++) {
            #pragma unroll
            for (int h2 = 0; h2 < 2; h2++) {
                int ml = wm * 64 + mi * 16 + h2 * 8 + g;
                float bi = bias[mt * 128 + ml];
                #pragma unroll
                for (int nj = 0; nj < 4; nj++) {
                    int ll = wn * 32 + nj * 8 + 2 * tg;
                    float v0 = acc[mi][nj][h2 * 2 + 0] + bi;
                    float v1 = acc[mi][nj][h2 * 2 + 1] + bi;
                    if (act) {
                        v0 = v0 > 0.f ? v0 : expm1f(v0);
                        v1 = v1 > 0.f ? v1 : expm1f(v1);
                    }
                    smh[(uint32_t)ll * 136 + ml]       = __float2half(v0);
                    smh[(uint32_t)(ll + 1) * 136 + ml] = __float2half(v1);
                }
            }
        }
        __syncthreads();
        int rowbase = (lt & 1) * 128;
        int NCo = M >> 6;
        #pragma unroll
        for (int kc = 0; kc < 2; kc++) {
            char* db = (char*)(Outh + (((size_t)b * 16 + lt256) * NCo + (mt * 2 + kc)) * 16384);
            #pragma unroll
            for (int it = 0; it < 4; it++) {
                int u = tid + 256 * it;
                int row = u >> 3, j = u & 7;
                uint4 w = *(uint4*)&smh[(uint32_t)row * 136 + kc * 64 + j * 8];
                *(uint4*)(db + swz128((uint32_t)(rowbase + row) * 128 + j * 16)) = w;
            }
        }
    }
}

// ---------------------------------------------------------------------------
// ctx via tensor cores: per (bh, sp) accumulate over l in chunks of 64:
//   A = exp(k) [64 dk x 64 l] fp16 (exp computed inline, fp32, rounded),
//   B = v      [64 dv x 64 l] fp16; ctx += A @ B^T ; Z[dk] += row-sums.
// 256 threads, 8 warps of 16dk x 32dv. grid (64, NSPLIT).
// ---------------------------------------------------------------------------
__global__ __launch_bounds__(256) void ctx_mma(
    const __half* __restrict__ kk, const __half* __restrict__ vv,
    float* __restrict__ ctxp, float* __restrict__ zp)
{
    __shared__ __align__(1024) char smem[16384];
    uint32_t sb = smem_u32(smem);
    int bh = blockIdx.x, sp = blockIdx.y;
    int tid = threadIdx.x, wid = tid >> 5, lane = tid & 31;
    const __half* kb = kk + (size_t)bh * Dh * Ln;
    const __half* vb = vv + (size_t)bh * Dh * Ln;

    // loader mapping: row 0..63, two uint4 (16 halves) per thread per tile
    int lrow = tid >> 2;
    int lu = (tid & 3) * 2;
    uint32_t sw0 = swz128((uint32_t)lrow * 128 + lu * 16);
    uint32_t sw1 = swz128((uint32_t)lrow * 128 + lu * 16 + 16);

    // mma mapping: warp -> 16 dk x 32 dv
    int mtile = wid >> 1;
    int ntile = (wid & 1) * 32;
    int sub = lane >> 3, r7 = lane & 7;
    uint32_t aRowOff = (uint32_t)(mtile * 16 + (sub & 1) * 8 + r7) * 128;
    uint32_t aMask = (aRowOff >> 3) & 0x70;
    int kaddA = (sub >> 1) * 16;
    uint32_t bRowOff[2], bMask[2];
    int kaddB = (sub & 1) * 16;
    #pragma unroll
    for (int j = 0; j < 2; j++) {
        uint32_t row = (uint32_t)(ntile + j * 16 + (sub >> 1) * 8 + r7);
        bRowOff[j] = row * 128;
        bMask[j] = (bRowOff[j] >> 3) & 0x70;
    }

    float acc[4][4];
    #pragma unroll
    for (int i = 0; i < 4; i++)
        #pragma unroll
        for (int j = 0; j < 4; j++) acc[i][j] = 0.f;
    float zacc = 0.f;

    int lbeg = sp * (Ln / NSPLIT);
    const int NCH = (Ln / NSPLIT) / 64;   // 8
    for (int ch = 0; ch < NCH; ch++) {
        int l0 = lbeg + ch * 64;
        const __half* kr = kb + (size_t)lrow * Ln + l0 + lu * 8;
        const __half* vr = vb + (size_t)lrow * Ln + l0 + lu * 8;
        uint4 k0 = *(const uint4*)kr;
        uint4 k1 = *(const uint4*)(kr + 8);
        uint4 v0 = *(const uint4*)vr;
        uint4 v1 = *(const uint4*)(vr + 8);
        // exp(k) in fp32, accumulate Z, repack fp16
        uint32_t* kw;
        kw = (uint32_t*)&k0;
        #pragma unroll
        for (int i = 0; i < 4; i++) {
            float2 f = __half22float2(*(__half2*)&kw[i]);
            f.x = __expf(f.x); f.y = __expf(f.y);
            zacc += f.x + f.y;
            kw[i] = pack2h(f.x, f.y);
        }
        kw = (uint32_t*)&k1;
        #pragma unroll
        for (int i = 0; i < 4; i++) {
            float2 f = __half22float2(*(__half2*)&kw[i]);
            f.x = __expf(f.x); f.y = __expf(f.y);
            zacc += f.x + f.y;
            kw[i] = pack2h(f.x, f.y);
        }
        __syncthreads();   // prior chunk's ldmatrix done
        *(uint4*)(smem + sw0) = k0;
        *(uint4*)(smem + sw1) = k1;
        *(uint4*)(smem + 8192 + sw0) = v0;
        *(uint4*)(smem + 8192 + sw1) = v1;
        __syncthreads();
        #pragma unroll
        for (int kk2 = 0; kk2 < 4; kk2++) {
            int kbyte = kk2 * 32;
            uint32_t aa[4], bbv[8];
            LDSM4(aa, sb + aRowOff + (uint32_t)((kaddA + kbyte) ^ aMask));
            #pragma unroll
            for (int j = 0; j < 2; j++)
                LDSM4(&bbv[j * 4], sb + 8192 + bRowOff[j] + (uint32_t)((kaddB + kbyte) ^ bMask[j]));
            #pragma unroll
            for (int nj = 0; nj < 4; nj++)
                MMA16816(acc[nj], aa, &bbv[nj * 2]);
        }
    }

    // store ctx partials
    int g = lane >> 2, tg = lane & 3;
    float* cbase = ctxp + ((size_t)sp * 64 + bh) * 4096;
    #pragma unroll
    for (int nj = 0; nj < 4; nj++) {
        int dv = ntile + nj * 8 + 2 * tg;
        int dk0 = mtile * 16 + g;
        *(float2*)(cbase + (size_t)dk0 * 64 + dv)       = make_float2(acc[nj][0], acc[nj][1]);
        *(float2*)(cbase + (size_t)(dk0 + 8) * 64 + dv) = make_float2(acc[nj][2], acc[nj][3]);
    }
    // Z: reduce 4 lanes covering one dk row
    zacc += __shfl_xor_sync(0xFFFFFFFFu, zacc, 1);
    zacc += __shfl_xor_sync(0xFFFFFFFFu, zacc, 2);
    if ((tid & 3) == 0)
        zp[((size_t)sp * 64 + bh) * 64 + lrow] = zacc;
}

// ---------------------------------------------------------------------------
// att fused: normalize ctx by Z, head-softmax(q fp16) inline, fp16 tiled out
// ---------------------------------------------------------------------------
__global__ __launch_bounds__(256) void att_fused(
    const float* __restrict__ ctxp, const float* __restrict__ zp,
    const __half* __restrict__ qh, __half* __restrict__ attc)
{
    int bh = blockIdx.y;
    int b = bh >> 3, h = bh & 7;
    __shared__ float cs[64][64];
    __shared__ float zinv[64];
    int tid = threadIdx.x;

    if (tid < 64) {
        float zs = 0.f;
        #pragma unroll
        for (int s = 0; s < NSPLIT; s++)
            zs += zp[((size_t)s * 64 + bh) * 64 + tid];
        zinv[tid] = 1.f / zs;
    }
    __syncthreads();

    float4* cs4 = (float4*)cs;
    #pragma unroll
    for (int r = 0; r < 4; r++) {
        int idx = tid + 256 * r;
        float zi = zinv[idx >> 4];
        float4 sum = make_float4(0.f, 0.f, 0.f, 0.f);
        #pragma unroll
        for (int s = 0; s < NSPLIT; s++) {
            const float4* p = (const float4*)(ctxp + ((size_t)s * 64 + bh) * 4096);
            float4 t = p[idx];
            sum.x += t.x; sum.y += t.y; sum.z += t.z; sum.w += t.w;
        }
        sum.x *= zi; sum.y *= zi; sum.z *= zi; sum.w *= zi;
        cs4[idx] = sum;
    }
    __syncthreads();

    int l = blockIdx.x * 256 + tid;
    const __half* qb = qh + (size_t)bh * Dh * Ln + l;

    float qv[64];
    float mx = -1e30f;
    #pragma unroll
    for (int d = 0; d < 64; d++) {
        qv[d] = __half2float(qb[(size_t)d * Ln]);
        mx = fmaxf(mx, qv[d]);
    }
    float s = 0.f;
    #pragma unroll
    for (int d = 0; d < 64; d++) { qv[d] = __expf(qv[d] - mx); s += qv[d]; }
    float inv = 1.f / s;

    float acc[64];
    #pragma unroll
    for (int d = 0; d < 64; d++) acc[d] = 0.f;

    #pragma unroll 4
    for (int dk = 0; dk < 64; dk++) {
        float qq = qv[dk] * inv;
        #pragma unroll
        for (int j = 0; j < 16; j++) {
            float4 c4 = *(const float4*)&cs[dk][j * 4];
            acc[4 * j + 0] += c4.x * qq;
            acc[4 * j + 1] += c4.y * qq;
            acc[4 * j + 2] += c4.z * qq;
            acc[4 * j + 3] += c4.w * qq;
        }
    }

    char* db = (char*)(attc + (((size_t)b * 16 + blockIdx.x) * 8 + h) * 16384);
    #pragma unroll
    for (int j = 0; j < 8; j++) {
        uint4 w;
        w.x = pack2h(acc[8*j+0], acc[8*j+1]);
        w.y = pack2h(acc[8*j+2], acc[8*j+3]);
        w.z = pack2h(acc[8*j+4], acc[8*j+5]);
        w.w = pack2h(acc[8*j+6], acc[8*j+7]);
        *(uint4*)(db + swz128((uint32_t)tid * 128 + j * 16)) = w;
    }
}

// ---------------------------------------------------------------------------
// Channel LayerNorm over C=512, fp16 in -> fp32 out (single pass, reg cache)
// ---------------------------------------------------------------------------
__global__ __launch_bounds__(256) void ln_kernel(
    const __half* __restrict__ in, float* __restrict__ out,
    const float* __restrict__ g, const float* __restrict__ be)
{
    __shared__ float ss[8][32], sq[8][32], smean[32], srstd[32];
    int blk = blockIdx.x;
    int b = blk >> 7;
    int li = threadIdx.x & 31;
    int l = ((blk & 127) << 5) + li;
    int r = threadIdx.x >> 5;
    const __half* base = in + (size_t)b * Cc * Ln + l;

    float s = 0.f, s2 = 0.f;
    float x0[64];
    #pragma unroll
    for (int k2 = 0; k2 < 64; k2++) {
        int c = r * 64 + k2;
        float x = __half2float(base[(size_t)c * Ln]);
        x0[k2] = x;
        s += x; s2 += x * x;
    }
    ss[r][li] = s; sq[r][li] = s2;
    __syncthreads();
    if (r == 0) {
        float ts = ss[0][li], t2 = sq[0][li];
        #pragma unroll
        for (int rr = 1; rr < 8; rr++) { ts += ss[rr][li]; t2 += sq[rr][li]; }
        float mean = ts * (1.f / 512.f);
        float var = t2 * (1.f / 512.f) - mean * mean;
        smean[li] = mean;
        srstd[li] = rsqrtf(var + 1e-5f);
    }
    __syncthreads();
    float mean = smean[li], rstd = srstd[li];
    float* ob = out + (size_t)b * Cc * Ln + l;
    #pragma unroll
    for (int k2 = 0; k2 < 64; k2++) {
        int c = r * 64 + k2;
        ob[(size_t)c * Ln] = (x0[k2] - mean) * rstd * g[c] + be[c];
    }
}

// ---------------------------------------------------------------------------
// Channel LayerNorm, fp16 in -> fp16 tiled out
// ---------------------------------------------------------------------------
__global__ __launch_bounds__(256) void ln_h(
    const __half* __restrict__ in, __half* __restrict__ outc,
    const float* __restrict__ g, const float* __restrict__ be)
{
    __shared__ float ss[8][32], sq[8][32], smean[32], srstd[32];
    int blk = blockIdx.x;
    int b = blk >> 7;
    int li = threadIdx.x & 31;
    int l = ((blk & 127) << 5) + li;
    int r = threadIdx.x >> 5;
    const __half* base = in + (size_t)b * Cc * Ln + l;

    float s = 0.f, s2 = 0.f;
    float x0[64];
    #pragma unroll
    for (int k2 = 0; k2 < 64; k2++) {
        int c = r * 64 + k2;
        float x = __half2float(base[(size_t)c * Ln]);
        x0[k2] = x;
        s += x; s2 += x * x;
    }
    ss[r][li] = s; sq[r][li] = s2;
    __syncthreads();
    if (r == 0) {
        float ts = ss[0][li], t2 = sq[0][li];
        #pragma unroll
        for (int rr = 1; rr < 8; rr++) { ts += ss[rr][li]; t2 += sq[rr][li]; }
        float mean = ts * (1.f / 512.f);
        float var = t2 * (1.f / 512.f) - mean * mean;
        smean[li] = mean;
        srstd[li] = rsqrtf(var + 1e-5f);
    }
    __syncthreads();
    float mean = smean[li], rstd = srstd[li];

    char* db = (char*)(outc + (((size_t)b * 16 + (l >> 8)) * 8 + r) * 16384);
    uint32_t row = (uint32_t)(l & 255);
    #pragma unroll
    for (int j = 0; j < 8; j++) {
        float v[8];
        #pragma unroll
        for (int q2 = 0; q2 < 8; q2++) {
            int c = r * 64 + j * 8 + q2;
            v[q2] = (x0[j * 8 + q2] - mean) * rstd * g[c] + be[c];
        }
        uint4 w;
        w.x = pack2h(v[0], v[1]);
        w.y = pack2h(v[2], v[3]);
        w.z = pack2h(v[4], v[5]);
        w.w = pack2h(v[6], v[7]);
        *(uint4*)(db + swz128(row * 128 + j * 16)) = w;
    }
}

// ---------------------------------------------------------------------------
extern "C" void kernel_launch(void* const* d_in, const int* in_sizes, int n_in,
                              void* d_out, int out_size)
{
    const float* z1  = (const float*)d_in[0];
    const float* z2  = (const float*)d_in[1];
    const float* Wq  = (const float*)d_in[2];
    const float* bq  = (const float*)d_in[3];
    const float* Wk  = (const float*)d_in[4];
    const float* bkb = (const float*)d_in[5];
    const float* Wv  = (const float*)d_in[6];
    const float* bv  = (const float*)d_in[7];
    const float* Wr  = (const float*)d_in[8];
    const float* br  = (const float*)d_in[9];
    const float* g1  = (const float*)d_in[10];
    const float* be1 = (const float*)d_in[11];
    const float* W1  = (const float*)d_in[12];
    const float* b1  = (const float*)d_in[13];
    const float* W2  = (const float*)d_in[14];
    const float* b2  = (const float*)d_in[15];
    const float* g2  = (const float*)d_in[16];
    const float* be2 = (const float*)d_in[17];

    float* fs = nullptr;
    cudaGetSymbolAddress((void**)&fs, g_scratch);
    __half* hf = nullptr;
    cudaGetSymbolAddress((void**)&hf, g_hf);

    const size_t SZ = (size_t)Bn * Cc * Ln;   // 16777216
    __half* qh  = (__half*)(fs);
    __half* kh  = (__half*)(fs + SZ);
    __half* vh  = (__half*)(fs + 2 * SZ);
    __half* zh  = (__half*)(fs + 4 * SZ);
    __half* yh  = (__half*)(fs + 5 * SZ);
    float* ctxp = fs + 6 * SZ;                // NSPLIT*64*64*64 floats
    float* zp   = fs + 7 * SZ;                // NSPLIT*64*64 floats

    cudaFuncSetAttribute(gemm_wm, cudaFuncAttributeMaxDynamicSharedMemorySize, GEMM_SMEM);
    cudaFuncSetAttribute(gemm_qkv, cudaFuncAttributeMaxDynamicSharedMemorySize, GEMM_SMEM);

    dim3 thr(256);
    conv_w_all<<<dim3(16, 8, 6), thr>>>(Wq, Wk, Wv, Wr, W1, W2, hf);
    conv_x2<<<dim3(8, 16, 16), thr>>>(z1, z2, hf + OFF_Z1C, hf + OFF_Z2C);

    // Merged Q/K/V projections (all fp16 flat)
    gemm_qkv<<<dim3(4, 32, 24), thr, GEMM_SMEM>>>(hf, bq, bkb, bv, qh, kh, vh);

    // Attention core: ctx on tensor cores (exp folded), then fused att
    ctx_mma<<<dim3(Bn * Hh, NSPLIT), thr>>>(kh, vh, ctxp, zp);
    att_fused<<<dim3(Ln / 256, Bn * Hh), thr>>>(ctxp, zp, qh, hf + OFF_ATTC);

    // Reprojection + residual -> fp16 flat z
    gemm_wm<<<dim3(4, 32, 8), thr, GEMM_SMEM>>>(hf + OFF_WR, br, hf + OFF_ATTC, nullptr, zh, z1, 512, 512, 0, 2);

    // LN1 (fp16 in) -> fp16 tiled
    ln_h<<<Bn * (Ln / 32), thr>>>(zh, hf + OFF_ZC, g1, be1);

    // FFN1 -> fp16 tiled h (ELU fused), FFN2 -> fp16 flat y
    gemm_wm<<<dim3(8, 32, 8), thr, GEMM_SMEM>>>(hf + OFF_W1, b1, hf + OFF_ZC, nullptr, hf + OFF_HC, nullptr, 1024, 512, 1, 1);
    gemm_wm<<<dim3(4, 32, 8), thr, GEMM_SMEM>>>(hf + OFF_W2, b2, hf + OFF_HC, nullptr, yh, nullptr, 512, 1024, 0, 2);

    // LN2 (fp16 in) -> fp32 output
    ln_kernel<<<Bn * (Ln / 32), thr>>>(yh, (float*)d_out, g2, be2);
}